// round 4
// baseline (speedup 1.0000x reference)
#include <cuda_runtime.h>
#include <math.h>

#define NNODES 10000
#define NEDGES 320000
#define ETOT   (NNODES + NEDGES)
#define HCOL   512          // HID*HEADS
#define H12    4
#define C12    128
#define C3     500
#define BN_EPS 1e-5f
#define NEG_SLOPE 0.2f

#define NEG_INF __int_as_float(0xff800000)

// ---------------- scratch (static __device__, no allocation) ----------------
__device__ float g_xp[NNODES * HCOL];      // transformed features (also holds [N,500] ld=500 for L3)
__device__ float g_h [NNODES * HCOL];      // aggregated / activated features
__device__ float g_s [NNODES * H12];
__device__ float g_d [NNODES * H12];
__device__ int   g_deg[NNODES];
__device__ int   g_off[NNODES + 1];
__device__ int   g_cur[NNODES];
__device__ int   g_csr[ETOT];
__device__ float g_bnsum[HCOL], g_bnsq[HCOL], g_bnscale[HCOL], g_bnshift[HCOL];

// ---------------- CSR build ----------------
__global__ void k_init_deg() {
    int i = blockIdx.x * blockDim.x + threadIdx.x;
    if (i < NNODES) g_deg[i] = 1;          // self loop
}

__global__ void k_hist(const int* __restrict__ ei) {
    int i = blockIdx.x * blockDim.x + threadIdx.x;
    if (i < NEDGES) atomicAdd(&g_deg[ei[NEDGES + i]], 1);   // dst row
}

__global__ void k_scan() {                  // single block, 1024 threads
    __shared__ int sm[1024];
    __shared__ int carry;
    int t = threadIdx.x;
    if (t == 0) carry = 0;
    __syncthreads();
    for (int base = 0; base < NNODES; base += 1024) {
        int i = base + t;
        int v = (i < NNODES) ? g_deg[i] : 0;
        sm[t] = v; __syncthreads();
        for (int off = 1; off < 1024; off <<= 1) {
            int tv = (t >= off) ? sm[t - off] : 0;
            __syncthreads();
            sm[t] += tv;
            __syncthreads();
        }
        int excl = sm[t] - v;
        if (i < NNODES) { g_off[i] = carry + excl; g_cur[i] = carry + excl; }
        __syncthreads();
        if (t == 1023) carry += sm[1023];
        __syncthreads();
    }
    if (t == 0) g_off[NNODES] = carry;      // = ETOT
}

__global__ void k_scatter(const int* __restrict__ ei) {
    int i = blockIdx.x * blockDim.x + threadIdx.x;
    if (i < NEDGES) {
        int s = ei[i], dst = ei[NEDGES + i];
        int p = atomicAdd(&g_cur[dst], 1);
        g_csr[p] = s;
    } else if (i < NEDGES + NNODES) {
        int nid = i - NEDGES;               // self loop
        int p = atomicAdd(&g_cur[nid], 1);
        g_csr[p] = nid;
    }
}

// ---------------- SGEMM: C[M,Ncols] = A[M,K] @ B[K,Ncols] (fp32) ----------------
// BM=128 BN=128 BK=16, 256 threads, 8x8 per thread. K%16==0, Ncols%4==0.
__global__ __launch_bounds__(256) void k_gemm(
    const float* __restrict__ A, const float* __restrict__ B, float* __restrict__ C,
    int M, int K, int Ncols, int ldc)
{
    __shared__ float As[16][128];
    __shared__ float Bs[16][128];
    int tid = threadIdx.x;
    int row0 = blockIdx.y * 128, col0 = blockIdx.x * 128;
    int tx = tid & 15, ty = tid >> 4;
    float acc[8][8];
#pragma unroll
    for (int i = 0; i < 8; i++)
#pragma unroll
        for (int j = 0; j < 8; j++) acc[i][j] = 0.f;

    for (int k0 = 0; k0 < K; k0 += 16) {
#pragma unroll
        for (int it = 0; it < 2; it++) {
            int e = tid + it * 256;         // 0..511
            int ar = e >> 2;                // 0..127
            int ak = (e & 3) * 4;
            float4 va = make_float4(0.f, 0.f, 0.f, 0.f);
            int gr = row0 + ar;
            if (gr < M) va = *(const float4*)(A + (size_t)gr * K + k0 + ak);
            As[ak + 0][ar] = va.x; As[ak + 1][ar] = va.y;
            As[ak + 2][ar] = va.z; As[ak + 3][ar] = va.w;

            int br = e >> 5;                // 0..15
            int bc = (e & 31) * 4;
            float4 vb = make_float4(0.f, 0.f, 0.f, 0.f);
            int gc = col0 + bc;
            if (gc < Ncols) vb = *(const float4*)(B + (size_t)(k0 + br) * Ncols + gc);
            *(float4*)&Bs[br][bc] = vb;
        }
        __syncthreads();
#pragma unroll
        for (int k = 0; k < 16; k++) {
            float a[8], b[8];
            *(float4*)&a[0] = *(float4*)&As[k][ty * 8];
            *(float4*)&a[4] = *(float4*)&As[k][ty * 8 + 4];
            *(float4*)&b[0] = *(float4*)&Bs[k][tx * 8];
            *(float4*)&b[4] = *(float4*)&Bs[k][tx * 8 + 4];
#pragma unroll
            for (int i = 0; i < 8; i++)
#pragma unroll
                for (int j = 0; j < 8; j++) acc[i][j] += a[i] * b[j];
        }
        __syncthreads();
    }
#pragma unroll
    for (int i = 0; i < 8; i++) {
        int r = row0 + ty * 8 + i;
        if (r >= M) continue;
#pragma unroll
        for (int j = 0; j < 8; j++) {
            int c = col0 + tx * 8 + j;
            if (c < Ncols) C[(size_t)r * ldc + c] = acc[i][j];
        }
    }
}

// ---------------- per-(node,head) attention logits ----------------
__global__ void k_logits(const float* __restrict__ xp, const float* __restrict__ a_src,
                         const float* __restrict__ a_dst, float* __restrict__ s,
                         float* __restrict__ d, int n, int H, int C, int ld)
{
    int w = (blockIdx.x * blockDim.x + threadIdx.x) >> 5;
    int lane = threadIdx.x & 31;
    if (w >= n * H) return;
    int node = w / H, h = w - node * H;
    const float* row = xp + (size_t)node * ld + h * C;
    float ss = 0.f, dd = 0.f;
    for (int c = lane; c < C; c += 32) {
        float v = row[c];
        ss += v * a_src[h * C + c];
        dd += v * a_dst[h * C + c];
    }
#pragma unroll
    for (int o = 16; o; o >>= 1) {
        ss += __shfl_xor_sync(0xffffffffu, ss, o);
        dd += __shfl_xor_sync(0xffffffffu, dd, o);
    }
    if (lane == 0) { s[w] = ss; d[w] = dd; }
}

// ---------------- aggregation: warp per (node,head), online softmax over in-edges ----
template <int NR, bool GUARD>
__global__ void k_agg(const float* __restrict__ xp, const float* __restrict__ s,
                      const float* __restrict__ dl, const float* __restrict__ bias,
                      float* __restrict__ out, int n, int H, int C, int ldxp, int ldout)
{
    int w = (blockIdx.x * blockDim.x + threadIdx.x) >> 5;
    int lane = threadIdx.x & 31;
    if (w >= n * H) return;
    int node = w / H, h = w - node * H;
    float m = NEG_INF, z = 0.f;
    float acc[NR];
#pragma unroll
    for (int r = 0; r < NR; r++) acc[r] = 0.f;
    float dn = dl[w];
    int beg = g_off[node], end = g_off[node + 1];
    for (int idx = beg; idx < end; idx++) {
        int src = g_csr[idx];
        float e = s[src * H + h] + dn;
        e = (e > 0.f) ? e : NEG_SLOPE * e;
        float mn = fmaxf(m, e);
        float scale = __expf(m - mn);       // m=-inf first edge -> 0
        float p = __expf(e - mn);
        z = z * scale + p;
        const float* row = xp + (size_t)src * ldxp + h * C;
#pragma unroll
        for (int r = 0; r < NR; r++) {
            int c = lane + r * 32;
            float v = (!GUARD || c < C) ? row[c] : 0.f;
            acc[r] = acc[r] * scale + p * v;
        }
        m = mn;
    }
    float inv = 1.f / z;
    float* orow = out + (size_t)node * ldout + h * C;
#pragma unroll
    for (int r = 0; r < NR; r++) {
        int c = lane + r * 32;
        if (!GUARD || c < C) orow[c] = acc[r] * inv + bias[h * C + c];
    }
}

// ---------------- batch norm + ELU ----------------
__global__ void k_bn_zero() {
    int i = blockIdx.x * blockDim.x + threadIdx.x;
    if (i < HCOL) { g_bnsum[i] = 0.f; g_bnsq[i] = 0.f; }
}

__global__ __launch_bounds__(256) void k_bn_stats(const float* __restrict__ x, int n) {
    int tid = threadIdx.x;                  // owns cols tid, tid+256
    int r0 = blockIdx.x * 64;
    int r1 = min(r0 + 64, n);
    float s0 = 0.f, s1 = 0.f, q0 = 0.f, q1 = 0.f;
    for (int r = r0; r < r1; r++) {
        float v0 = x[(size_t)r * HCOL + tid];
        float v1 = x[(size_t)r * HCOL + tid + 256];
        s0 += v0; q0 += v0 * v0;
        s1 += v1; q1 += v1 * v1;
    }
    atomicAdd(&g_bnsum[tid],       s0);
    atomicAdd(&g_bnsq [tid],       q0);
    atomicAdd(&g_bnsum[tid + 256], s1);
    atomicAdd(&g_bnsq [tid + 256], q1);
}

__global__ void k_bn_finalize(const float* __restrict__ gamma, const float* __restrict__ beta, int n) {
    int c = blockIdx.x * blockDim.x + threadIdx.x;
    if (c >= HCOL) return;
    float mu = g_bnsum[c] / (float)n;
    float var = g_bnsq[c] / (float)n - mu * mu;
    float sc = gamma[c] * rsqrtf(var + BN_EPS);
    g_bnscale[c] = sc;
    g_bnshift[c] = beta[c] - mu * sc;
}

__global__ void k_bn_apply_elu(float* __restrict__ x, int n) {
    int i = blockIdx.x * blockDim.x + threadIdx.x;
    if (i >= n * HCOL) return;
    int c = i & (HCOL - 1);
    float v = x[i] * g_bnscale[c] + g_bnshift[c];
    x[i] = (v > 0.f) ? v : expm1f(v);
}

// ---------------- launch ----------------
extern "C" void kernel_launch(void* const* d_in, const int* in_sizes, int n_in,
                              void* d_out, int out_size)
{
    const float* x      = (const float*)d_in[0];
    const int*   ei     = (const int*)  d_in[1];
    const float* W1     = (const float*)d_in[2];
    const float* a_src1 = (const float*)d_in[3];
    const float* a_dst1 = (const float*)d_in[4];
    const float* b1     = (const float*)d_in[5];
    const float* g1     = (const float*)d_in[6];
    const float* be1    = (const float*)d_in[7];
    const float* W2     = (const float*)d_in[8];
    const float* a_src2 = (const float*)d_in[9];
    const float* a_dst2 = (const float*)d_in[10];
    const float* b2     = (const float*)d_in[11];
    const float* g2     = (const float*)d_in[12];
    const float* be2    = (const float*)d_in[13];
    const float* W3     = (const float*)d_in[14];
    const float* a_src3 = (const float*)d_in[15];
    const float* a_dst3 = (const float*)d_in[16];
    const float* b3     = (const float*)d_in[17];
    float* out = (float*)d_out;

    float *xp, *h, *s, *d;
    cudaGetSymbolAddress((void**)&xp, g_xp);
    cudaGetSymbolAddress((void**)&h,  g_h);
    cudaGetSymbolAddress((void**)&s,  g_s);
    cudaGetSymbolAddress((void**)&d,  g_d);

    const int n = NNODES;

    // CSR build
    k_init_deg<<<(n + 255) / 256, 256>>>();
    k_hist<<<(NEDGES + 255) / 256, 256>>>(ei);
    k_scan<<<1, 1024>>>();
    k_scatter<<<(NEDGES + n + 255) / 256, 256>>>(ei);

    dim3 gemmGrid(4, (n + 127) / 128);
    int warpBlocks12 = (n * H12 * 32 + 255) / 256;   // warp per (node,head)
    int warpBlocks3  = (n * 32 + 255) / 256;

    // ---- layer 1 ----
    k_gemm<<<gemmGrid, 256>>>(x, W1, xp, n, 1280, HCOL, HCOL);
    k_logits<<<warpBlocks12, 256>>>(xp, a_src1, a_dst1, s, d, n, H12, C12, HCOL);
    k_agg<4, false><<<warpBlocks12, 256>>>(xp, s, d, b1, h, n, H12, C12, HCOL, HCOL);
    k_bn_zero<<<2, 256>>>();
    k_bn_stats<<<(n + 63) / 64, 256>>>(h, n);
    k_bn_finalize<<<2, 256>>>(g1, be1, n);
    k_bn_apply_elu<<<(n * HCOL + 255) / 256, 256>>>(h, n);

    // ---- layer 2 ----
    k_gemm<<<gemmGrid, 256>>>(h, W2, xp, n, HCOL, HCOL, HCOL);
    k_logits<<<warpBlocks12, 256>>>(xp, a_src2, a_dst2, s, d, n, H12, C12, HCOL);
    k_agg<4, false><<<warpBlocks12, 256>>>(xp, s, d, b2, h, n, H12, C12, HCOL, HCOL);
    k_bn_zero<<<2, 256>>>();
    k_bn_stats<<<(n + 63) / 64, 256>>>(h, n);
    k_bn_finalize<<<2, 256>>>(g2, be2, n);
    k_bn_apply_elu<<<(n * HCOL + 255) / 256, 256>>>(h, n);

    // ---- layer 3 (H=1, C=500, mean over 1 head == identity) ----
    k_gemm<<<gemmGrid, 256>>>(h, W3, xp, n, HCOL, C3, C3);
    k_logits<<<warpBlocks3, 256>>>(xp, a_src3, a_dst3, s, d, n, 1, C3, C3);
    k_agg<16, true><<<warpBlocks3, 256>>>(xp, s, d, b3, out, n, 1, C3, C3, C3);
}

// round 8
// speedup vs baseline: 1.9089x; 1.9089x over previous
#include <cuda_runtime.h>
#include <math.h>
#include <stdint.h>

#define NNODES 10000
#define NEDGES 320000
#define ETOT   (NNODES + NEDGES)
#define HCOL   512          // HID*HEADS
#define H12    4
#define C12    128
#define C3     500
#define BN_EPS 1e-5f
#define NEG_SLOPE 0.2f

#define NEG_INF __int_as_float(0xff800000)

// ---------------- scratch (static __device__, no allocation) ----------------
__device__ float g_xp[NNODES * HCOL];      // transformed features (ld=500 for L3)
__device__ float g_h [NNODES * HCOL];      // aggregated / activated features
__device__ float g_s [NNODES * H12];
__device__ float g_d [NNODES * H12];
__device__ int   g_deg[NNODES];
__device__ int   g_off[NNODES + 1];
__device__ int   g_cur[NNODES];
__device__ int   g_csr[ETOT];
__device__ float g_bnsum[HCOL], g_bnsq[HCOL], g_bnscale[HCOL], g_bnshift[HCOL];

// ---------------- CSR build ----------------
__global__ void k_init_deg() {
    int i = blockIdx.x * blockDim.x + threadIdx.x;
    if (i < NNODES) g_deg[i] = 1;          // self loop
}

__global__ void k_hist(const int* __restrict__ ei) {
    int i = blockIdx.x * blockDim.x + threadIdx.x;
    if (i < NEDGES) atomicAdd(&g_deg[ei[NEDGES + i]], 1);   // dst row
}

__global__ void k_scan() {                  // single block, 1024 threads
    __shared__ int sm[1024];
    __shared__ int carry;
    int t = threadIdx.x;
    if (t == 0) carry = 0;
    __syncthreads();
    for (int base = 0; base < NNODES; base += 1024) {
        int i = base + t;
        int v = (i < NNODES) ? g_deg[i] : 0;
        sm[t] = v; __syncthreads();
        for (int off = 1; off < 1024; off <<= 1) {
            int tv = (t >= off) ? sm[t - off] : 0;
            __syncthreads();
            sm[t] += tv;
            __syncthreads();
        }
        int excl = sm[t] - v;
        if (i < NNODES) { g_off[i] = carry + excl; g_cur[i] = carry + excl; }
        __syncthreads();
        if (t == 1023) carry += sm[1023];
        __syncthreads();
    }
    if (t == 0) g_off[NNODES] = carry;      // = ETOT
}

__global__ void k_scatter(const int* __restrict__ ei) {
    int i = blockIdx.x * blockDim.x + threadIdx.x;
    if (i < NEDGES) {
        int s = ei[i], dst = ei[NEDGES + i];
        int p = atomicAdd(&g_cur[dst], 1);
        g_csr[p] = s;
    } else if (i < NEDGES + NNODES) {
        int nid = i - NEDGES;               // self loop
        int p = atomicAdd(&g_cur[nid], 1);
        g_csr[p] = nid;
    }
}

// ---------------- TF32 tensor-core GEMM ----------------
// C[M,Ncols] = A[M,K] @ B[K,Ncols], fp32 in/out, tf32 mma.sync m16n8k8.
// BM=128 BN=128 BK=32, 256 threads (8 warps), warp tile 32x64.
// Requires K % 32 == 0, Ncols % 4 == 0 (both hold: 1280/512 K, 512/500 N).

__device__ __forceinline__ uint32_t f2tf32(float x) {
    uint32_t r;
    asm("cvt.rna.tf32.f32 %0, %1;" : "=r"(r) : "f"(x));
    return r;
}

__device__ __forceinline__ void mma_tf32(float* c, const uint32_t* a, const uint32_t* b) {
    asm volatile(
        "mma.sync.aligned.m16n8k8.row.col.f32.tf32.tf32.f32 "
        "{%0,%1,%2,%3}, {%4,%5,%6,%7}, {%8,%9}, {%0,%1,%2,%3};"
        : "+f"(c[0]), "+f"(c[1]), "+f"(c[2]), "+f"(c[3])
        : "r"(a[0]), "r"(a[1]), "r"(a[2]), "r"(a[3]), "r"(b[0]), "r"(b[1]));
}

#define AS_LD 132   // As[k][m], pad 4
#define BS_LD 136   // Bs[k][n], pad 8 -> conflict-free b-fragment LDS

__global__ __launch_bounds__(256) void k_gemm_tf32(
    const float* __restrict__ A, const float* __restrict__ B, float* __restrict__ C,
    int M, int K, int Ncols, int ldc)
{
    __shared__ uint32_t As[32][AS_LD];
    __shared__ uint32_t Bs[32][BS_LD];

    int tid  = threadIdx.x;
    int warp = tid >> 5, lane = tid & 31;
    int lr = lane >> 2, lc = lane & 3;
    int row0 = blockIdx.y * 128, col0 = blockIdx.x * 128;
    int wm = (warp & 3) * 32;      // warp m-offset within block
    int wn = (warp >> 2) * 64;     // warp n-offset within block

    float acc[2][8][4];
#pragma unroll
    for (int i = 0; i < 2; i++)
#pragma unroll
        for (int j = 0; j < 8; j++)
#pragma unroll
            for (int r = 0; r < 4; r++) acc[i][j][r] = 0.f;

    for (int k0 = 0; k0 < K; k0 += 32) {
        // --- load A tile (128 rows x 32 k), transpose into As[k][m], cvt tf32 ---
#pragma unroll
        for (int it = 0; it < 4; it++) {
            int c  = tid + it * 256;        // 0..1023 float4 chunks
            int r  = c >> 3;                // 0..127
            int kc = (c & 7) * 4;
            int gr = row0 + r;
            float4 v = make_float4(0.f, 0.f, 0.f, 0.f);
            if (gr < M) v = *(const float4*)(A + (size_t)gr * K + k0 + kc);
            As[kc + 0][r] = f2tf32(v.x);
            As[kc + 1][r] = f2tf32(v.y);
            As[kc + 2][r] = f2tf32(v.z);
            As[kc + 3][r] = f2tf32(v.w);
        }
        // --- load B tile (32 k x 128 n) into Bs[k][n], cvt tf32 ---
#pragma unroll
        for (int it = 0; it < 4; it++) {
            int c  = tid + it * 256;
            int kr = c >> 5;                // 0..31
            int nc = (c & 31) * 4;
            int gc = col0 + nc;
            float4 v = make_float4(0.f, 0.f, 0.f, 0.f);
            if (gc < Ncols) v = *(const float4*)(B + (size_t)(k0 + kr) * Ncols + gc);
            Bs[kr][nc + 0] = f2tf32(v.x);
            Bs[kr][nc + 1] = f2tf32(v.y);
            Bs[kr][nc + 2] = f2tf32(v.z);
            Bs[kr][nc + 3] = f2tf32(v.w);
        }
        __syncthreads();

#pragma unroll
        for (int kk = 0; kk < 32; kk += 8) {
            uint32_t af[2][4], bf[8][2];
#pragma unroll
            for (int mi = 0; mi < 2; mi++) {
                int m = wm + mi * 16;
                af[mi][0] = As[kk + lc    ][m + lr];
                af[mi][1] = As[kk + lc    ][m + lr + 8];
                af[mi][2] = As[kk + lc + 4][m + lr];
                af[mi][3] = As[kk + lc + 4][m + lr + 8];
            }
#pragma unroll
            for (int ni = 0; ni < 8; ni++) {
                int nn = wn + ni * 8;
                bf[ni][0] = Bs[kk + lc    ][nn + lr];
                bf[ni][1] = Bs[kk + lc + 4][nn + lr];
            }
#pragma unroll
            for (int mi = 0; mi < 2; mi++)
#pragma unroll
                for (int ni = 0; ni < 8; ni++)
                    mma_tf32(acc[mi][ni], af[mi], bf[ni]);
        }
        __syncthreads();
    }

    // --- store C (Ncols even -> float2 pairs stay in-bounds together) ---
#pragma unroll
    for (int mi = 0; mi < 2; mi++) {
#pragma unroll
        for (int ni = 0; ni < 8; ni++) {
            int colb = col0 + wn + ni * 8 + lc * 2;
            if (colb >= Ncols) continue;
#pragma unroll
            for (int hh = 0; hh < 2; hh++) {
                int r = row0 + wm + mi * 16 + lr + hh * 8;
                if (r < M) {
                    float2 v = make_float2(acc[mi][ni][hh * 2], acc[mi][ni][hh * 2 + 1]);
                    *(float2*)(C + (size_t)r * ldc + colb) = v;
                }
            }
        }
    }
}

// ---------------- per-(node,head) attention logits ----------------
__global__ void k_logits(const float* __restrict__ xp, const float* __restrict__ a_src,
                         const float* __restrict__ a_dst, float* __restrict__ s,
                         float* __restrict__ d, int n, int H, int C, int ld)
{
    int w = (blockIdx.x * blockDim.x + threadIdx.x) >> 5;
    int lane = threadIdx.x & 31;
    if (w >= n * H) return;
    int node = w / H, h = w - node * H;
    const float* row = xp + (size_t)node * ld + h * C;
    float ss = 0.f, dd = 0.f;
    for (int c = lane; c < C; c += 32) {
        float v = row[c];
        ss += v * a_src[h * C + c];
        dd += v * a_dst[h * C + c];
    }
#pragma unroll
    for (int o = 16; o; o >>= 1) {
        ss += __shfl_xor_sync(0xffffffffu, ss, o);
        dd += __shfl_xor_sync(0xffffffffu, dd, o);
    }
    if (lane == 0) { s[w] = ss; d[w] = dd; }
}

// ---------------- aggregation: warp per (node,head), online softmax over in-edges ----
template <int NR, bool GUARD>
__global__ void k_agg(const float* __restrict__ xp, const float* __restrict__ s,
                      const float* __restrict__ dl, const float* __restrict__ bias,
                      float* __restrict__ out, int n, int H, int C, int ldxp, int ldout)
{
    int w = (blockIdx.x * blockDim.x + threadIdx.x) >> 5;
    int lane = threadIdx.x & 31;
    if (w >= n * H) return;
    int node = w / H, h = w - node * H;
    float m = NEG_INF, z = 0.f;
    float acc[NR];
#pragma unroll
    for (int r = 0; r < NR; r++) acc[r] = 0.f;
    float dn = dl[w];
    int beg = g_off[node], end = g_off[node + 1];
    for (int idx = beg; idx < end; idx++) {
        int src = g_csr[idx];
        float e = s[src * H + h] + dn;
        e = (e > 0.f) ? e : NEG_SLOPE * e;
        float mn = fmaxf(m, e);
        float scale = __expf(m - mn);       // m=-inf first edge -> 0
        float p = __expf(e - mn);
        z = z * scale + p;
        const float* row = xp + (size_t)src * ldxp + h * C;
#pragma unroll
        for (int r = 0; r < NR; r++) {
            int c = lane + r * 32;
            float v = (!GUARD || c < C) ? row[c] : 0.f;
            acc[r] = acc[r] * scale + p * v;
        }
        m = mn;
    }
    float inv = 1.f / z;
    float* orow = out + (size_t)node * ldout + h * C;
#pragma unroll
    for (int r = 0; r < NR; r++) {
        int c = lane + r * 32;
        if (!GUARD || c < C) orow[c] = acc[r] * inv + bias[h * C + c];
    }
}

// ---------------- batch norm + ELU ----------------
__global__ void k_bn_zero() {
    int i = blockIdx.x * blockDim.x + threadIdx.x;
    if (i < HCOL) { g_bnsum[i] = 0.f; g_bnsq[i] = 0.f; }
}

__global__ __launch_bounds__(256) void k_bn_stats(const float* __restrict__ x, int n) {
    int tid = threadIdx.x;                  // owns cols tid, tid+256
    int r0 = blockIdx.x * 64;
    int r1 = min(r0 + 64, n);
    float s0 = 0.f, s1 = 0.f, q0 = 0.f, q1 = 0.f;
    for (int r = r0; r < r1; r++) {
        float v0 = x[(size_t)r * HCOL + tid];
        float v1 = x[(size_t)r * HCOL + tid + 256];
        s0 += v0; q0 += v0 * v0;
        s1 += v1; q1 += v1 * v1;
    }
    atomicAdd(&g_bnsum[tid],       s0);
    atomicAdd(&g_bnsq [tid],       q0);
    atomicAdd(&g_bnsum[tid + 256], s1);
    atomicAdd(&g_bnsq [tid + 256], q1);
}

__global__ void k_bn_finalize(const float* __restrict__ gamma, const float* __restrict__ beta, int n) {
    int c = blockIdx.x * blockDim.x + threadIdx.x;
    if (c >= HCOL) return;
    float mu = g_bnsum[c] / (float)n;
    float var = g_bnsq[c] / (float)n - mu * mu;
    float sc = gamma[c] * rsqrtf(var + BN_EPS);
    g_bnscale[c] = sc;
    g_bnshift[c] = beta[c] - mu * sc;
}

__global__ void k_bn_apply_elu(float* __restrict__ x, int n) {
    int i = blockIdx.x * blockDim.x + threadIdx.x;
    if (i >= n * HCOL) return;
    int c = i & (HCOL - 1);
    float v = x[i] * g_bnscale[c] + g_bnshift[c];
    x[i] = (v > 0.f) ? v : expm1f(v);
}

// ---------------- launch ----------------
extern "C" void kernel_launch(void* const* d_in, const int* in_sizes, int n_in,
                              void* d_out, int out_size)
{
    const float* x      = (const float*)d_in[0];
    const int*   ei     = (const int*)  d_in[1];
    const float* W1     = (const float*)d_in[2];
    const float* a_src1 = (const float*)d_in[3];
    const float* a_dst1 = (const float*)d_in[4];
    const float* b1     = (const float*)d_in[5];
    const float* g1     = (const float*)d_in[6];
    const float* be1    = (const float*)d_in[7];
    const float* W2     = (const float*)d_in[8];
    const float* a_src2 = (const float*)d_in[9];
    const float* a_dst2 = (const float*)d_in[10];
    const float* b2     = (const float*)d_in[11];
    const float* g2     = (const float*)d_in[12];
    const float* be2    = (const float*)d_in[13];
    const float* W3     = (const float*)d_in[14];
    const float* a_src3 = (const float*)d_in[15];
    const float* a_dst3 = (const float*)d_in[16];
    const float* b3     = (const float*)d_in[17];
    float* out = (float*)d_out;

    float *xp, *h, *s, *d;
    cudaGetSymbolAddress((void**)&xp, g_xp);
    cudaGetSymbolAddress((void**)&h,  g_h);
    cudaGetSymbolAddress((void**)&s,  g_s);
    cudaGetSymbolAddress((void**)&d,  g_d);

    const int n = NNODES;

    // CSR build
    k_init_deg<<<(n + 255) / 256, 256>>>();
    k_hist<<<(NEDGES + 255) / 256, 256>>>(ei);
    k_scan<<<1, 1024>>>();
    k_scatter<<<(NEDGES + n + 255) / 256, 256>>>(ei);

    dim3 gemmGrid(4, (n + 127) / 128);
    int warpBlocks12 = (n * H12 * 32 + 255) / 256;   // warp per (node,head)
    int warpBlocks3  = (n * 32 + 255) / 256;

    // ---- layer 1 ----
    k_gemm_tf32<<<gemmGrid, 256>>>(x, W1, xp, n, 1280, HCOL, HCOL);
    k_logits<<<warpBlocks12, 256>>>(xp, a_src1, a_dst1, s, d, n, H12, C12, HCOL);
    k_agg<4, false><<<warpBlocks12, 256>>>(xp, s, d, b1, h, n, H12, C12, HCOL, HCOL);
    k_bn_zero<<<2, 256>>>();
    k_bn_stats<<<(n + 63) / 64, 256>>>(h, n);
    k_bn_finalize<<<2, 256>>>(g1, be1, n);
    k_bn_apply_elu<<<(n * HCOL + 255) / 256, 256>>>(h, n);

    // ---- layer 2 ----
    k_gemm_tf32<<<gemmGrid, 256>>>(h, W2, xp, n, HCOL, HCOL, HCOL);
    k_logits<<<warpBlocks12, 256>>>(xp, a_src2, a_dst2, s, d, n, H12, C12, HCOL);
    k_agg<4, false><<<warpBlocks12, 256>>>(xp, s, d, b2, h, n, H12, C12, HCOL, HCOL);
    k_bn_zero<<<2, 256>>>();
    k_bn_stats<<<(n + 63) / 64, 256>>>(h, n);
    k_bn_finalize<<<2, 256>>>(g2, be2, n);
    k_bn_apply_elu<<<(n * HCOL + 255) / 256, 256>>>(h, n);

    // ---- layer 3 (H=1, C=500, mean over 1 head == identity) ----
    k_gemm_tf32<<<gemmGrid, 256>>>(h, W3, xp, n, HCOL, C3, C3);
    k_logits<<<warpBlocks3, 256>>>(xp, a_src3, a_dst3, s, d, n, 1, C3, C3);
    k_agg<16, true><<<warpBlocks3, 256>>>(xp, s, d, b3, out, n, 1, C3, C3, C3);
}

// round 11
// speedup vs baseline: 2.1805x; 1.1423x over previous
#include <cuda_runtime.h>
#include <math.h>
#include <stdint.h>

#define NNODES 10000
#define NEDGES 320000
#define ETOT   (NNODES + NEDGES)
#define HCOL   512          // HID*HEADS
#define H12    4
#define C12    128
#define C3     500
#define BN_EPS 1e-5f
#define NEG_SLOPE 0.2f

#define NEG_INF __int_as_float(0xff800000)

// ---------------- scratch (static __device__, no allocation) ----------------
__device__ float g_xp[NNODES * HCOL];      // transformed features (ld=500 for L3)
__device__ float g_h [NNODES * HCOL];      // aggregated / activated features
__device__ float g_s [NNODES * H12];
__device__ float g_d [NNODES * H12];
__device__ int   g_deg[NNODES];
__device__ int   g_off[NNODES + 1];
__device__ int   g_cur[NNODES];
__device__ int   g_csr[ETOT];
__device__ float g_bnsum[HCOL], g_bnsq[HCOL], g_bnscale[HCOL], g_bnshift[HCOL];

// ---------------- CSR build ----------------
__global__ void k_init_deg() {
    int i = blockIdx.x * blockDim.x + threadIdx.x;
    if (i < NNODES) g_deg[i] = 1;          // self loop
}

__global__ void k_hist(const int* __restrict__ ei) {
    int i = blockIdx.x * blockDim.x + threadIdx.x;
    if (i < NEDGES) atomicAdd(&g_deg[ei[NEDGES + i]], 1);   // dst row
}

__global__ void k_scan() {                  // single block, 1024 threads
    __shared__ int sm[1024];
    __shared__ int carry;
    int t = threadIdx.x;
    if (t == 0) carry = 0;
    __syncthreads();
    for (int base = 0; base < NNODES; base += 1024) {
        int i = base + t;
        int v = (i < NNODES) ? g_deg[i] : 0;
        sm[t] = v; __syncthreads();
        for (int off = 1; off < 1024; off <<= 1) {
            int tv = (t >= off) ? sm[t - off] : 0;
            __syncthreads();
            sm[t] += tv;
            __syncthreads();
        }
        int excl = sm[t] - v;
        if (i < NNODES) { g_off[i] = carry + excl; g_cur[i] = carry + excl; }
        __syncthreads();
        if (t == 1023) carry += sm[1023];
        __syncthreads();
    }
    if (t == 0) g_off[NNODES] = carry;      // = ETOT
}

__global__ void k_scatter(const int* __restrict__ ei) {
    int i = blockIdx.x * blockDim.x + threadIdx.x;
    if (i < NEDGES) {
        int s = ei[i], dst = ei[NEDGES + i];
        int p = atomicAdd(&g_cur[dst], 1);
        g_csr[p] = s;
    } else if (i < NEDGES + NNODES) {
        int nid = i - NEDGES;               // self loop
        int p = atomicAdd(&g_cur[nid], 1);
        g_csr[p] = nid;
    }
}

// ---------------- TF32 tensor-core GEMM, cp.async 3-stage pipeline ----------------
// C[M,Ncols] = A[M,K] @ B[K,Ncols], fp32 in/out, tf32 mma.sync m16n8k8.
// BM=128 BN=128 BK=32, 256 threads (8 warps), warp tile 32x64.
// Raw fp32 tiles in smem (cp.async, clamped in-bounds addresses),
// cvt.rna.tf32 applied at fragment load (same rounding path as round 8).
// A stride 36 (=4 mod 32), B stride 136 (=8 mod 32) -> conflict-free frag LDS.

#define AS_STRIDE 36
#define BS_STRIDE 136
#define A_TILE (128 * AS_STRIDE)
#define B_TILE (32 * BS_STRIDE)
#define NSTAGE 3
#define SMEM_GEMM (NSTAGE * (A_TILE + B_TILE) * 4)

__device__ __forceinline__ uint32_t f2tf32(float x) {
    uint32_t r;
    asm("cvt.rna.tf32.f32 %0, %1;" : "=r"(r) : "f"(x));
    return r;
}

__device__ __forceinline__ void mma_tf32(float* c, const uint32_t* a, const uint32_t* b) {
    asm volatile(
        "mma.sync.aligned.m16n8k8.row.col.f32.tf32.tf32.f32 "
        "{%0,%1,%2,%3}, {%4,%5,%6,%7}, {%8,%9}, {%0,%1,%2,%3};"
        : "+f"(c[0]), "+f"(c[1]), "+f"(c[2]), "+f"(c[3])
        : "r"(a[0]), "r"(a[1]), "r"(a[2]), "r"(a[3]), "r"(b[0]), "r"(b[1]));
}

__device__ __forceinline__ void cp16(float* dst, const float* src) {
    uint32_t d = (uint32_t)__cvta_generic_to_shared(dst);
    asm volatile("cp.async.cg.shared.global [%0], [%1], 16;"
                 :: "r"(d), "l"(src) : "memory");
}

__device__ __forceinline__ void load_tile(
    const float* __restrict__ A, const float* __restrict__ B,
    int M, int K, int Ncols, int row0, int col0, int k0,
    float* As_st, float* Bs_st, int tid)
{
#pragma unroll
    for (int it = 0; it < 4; it++) {
        int e = tid + it * 256;             // 0..1023
        int r = e >> 3;                     // 0..127
        int kc = (e & 7) * 4;
        int gr = row0 + r;
        if (gr >= M) gr = M - 1;            // clamp: garbage rows never stored
        cp16(As_st + r * AS_STRIDE + kc, A + (size_t)gr * K + k0 + kc);
    }
#pragma unroll
    for (int it = 0; it < 4; it++) {
        int e = tid + it * 256;
        int kr = e >> 5;                    // 0..31
        int nc = (e & 31) * 4;
        int gc = col0 + nc;
        if (gc >= Ncols) gc = Ncols - 4;    // clamp: garbage cols never stored
        cp16(Bs_st + kr * BS_STRIDE + nc, B + (size_t)(k0 + kr) * Ncols + gc);
    }
}

__global__ __launch_bounds__(256) void k_gemm_tf32(
    const float* __restrict__ A, const float* __restrict__ B, float* __restrict__ C,
    int M, int K, int Ncols, int ldc)
{
    extern __shared__ float smp[];
    float* As = smp;                        // [NSTAGE][A_TILE]
    float* Bs = smp + NSTAGE * A_TILE;      // [NSTAGE][B_TILE]

    int tid  = threadIdx.x;
    int warp = tid >> 5, lane = tid & 31;
    int lr = lane >> 2, lc = lane & 3;
    int row0 = blockIdx.y * 128, col0 = blockIdx.x * 128;
    int wm = (warp & 3) * 32;               // warp m-offset
    int wn = (warp >> 2) * 64;              // warp n-offset

    float acc[2][8][4];
#pragma unroll
    for (int i = 0; i < 2; i++)
#pragma unroll
        for (int j = 0; j < 8; j++)
#pragma unroll
            for (int r = 0; r < 4; r++) acc[i][j][r] = 0.f;

    int T = K >> 5;                         // K % 32 == 0 always

    load_tile(A, B, M, K, Ncols, row0, col0, 0, As, Bs, tid);
    asm volatile("cp.async.commit_group;" ::: "memory");
    load_tile(A, B, M, K, Ncols, row0, col0, 32, As + A_TILE, Bs + B_TILE, tid);
    asm volatile("cp.async.commit_group;" ::: "memory");

    for (int kt = 0; kt < T; kt++) {
        if (kt + 2 < T) {
            int st = (kt + 2) % NSTAGE;
            load_tile(A, B, M, K, Ncols, row0, col0, (kt + 2) * 32,
                      As + st * A_TILE, Bs + st * B_TILE, tid);
        }
        asm volatile("cp.async.commit_group;" ::: "memory");
        asm volatile("cp.async.wait_group 2;" ::: "memory");
        __syncthreads();

        const float* a_s = As + (kt % NSTAGE) * A_TILE;
        const float* b_s = Bs + (kt % NSTAGE) * B_TILE;

#pragma unroll
        for (int kk = 0; kk < 32; kk += 8) {
            uint32_t af[2][4], bf[8][2];
#pragma unroll
            for (int mi = 0; mi < 2; mi++) {
                int m = wm + mi * 16;
                af[mi][0] = f2tf32(a_s[(m + lr    ) * AS_STRIDE + kk + lc    ]);
                af[mi][1] = f2tf32(a_s[(m + lr + 8) * AS_STRIDE + kk + lc    ]);
                af[mi][2] = f2tf32(a_s[(m + lr    ) * AS_STRIDE + kk + lc + 4]);
                af[mi][3] = f2tf32(a_s[(m + lr + 8) * AS_STRIDE + kk + lc + 4]);
            }
#pragma unroll
            for (int ni = 0; ni < 8; ni++) {
                int nn = wn + ni * 8;
                bf[ni][0] = f2tf32(b_s[(kk + lc    ) * BS_STRIDE + nn + lr]);
                bf[ni][1] = f2tf32(b_s[(kk + lc + 4) * BS_STRIDE + nn + lr]);
            }
#pragma unroll
            for (int mi = 0; mi < 2; mi++)
#pragma unroll
                for (int ni = 0; ni < 8; ni++)
                    mma_tf32(acc[mi][ni], af[mi], bf[ni]);
        }
        __syncthreads();
    }

    // --- store C (Ncols % 4 == 0 -> float2 pairs stay in-bounds together) ---
#pragma unroll
    for (int mi = 0; mi < 2; mi++) {
#pragma unroll
        for (int ni = 0; ni < 8; ni++) {
            int colb = col0 + wn + ni * 8 + lc * 2;
            if (colb >= Ncols) continue;
#pragma unroll
            for (int hh = 0; hh < 2; hh++) {
                int r = row0 + wm + mi * 16 + lr + hh * 8;
                if (r < M) {
                    float2 v = make_float2(acc[mi][ni][hh * 2], acc[mi][ni][hh * 2 + 1]);
                    *(float2*)(C + (size_t)r * ldc + colb) = v;
                }
            }
        }
    }
}

// ---------------- per-(node,head) attention logits (float4) ----------------
__global__ void k_logits(const float* __restrict__ xp, const float* __restrict__ a_src,
                         const float* __restrict__ a_dst, float* __restrict__ s,
                         float* __restrict__ d, int n, int H, int C, int ld)
{
    int w = (blockIdx.x * blockDim.x + threadIdx.x) >> 5;
    int lane = threadIdx.x & 31;
    if (w >= n * H) return;
    int node = w / H, h = w - node * H;
    int C4 = C >> 2;                        // C % 4 == 0 (128, 500)
    const float4* row = (const float4*)(xp + (size_t)node * ld + h * C);
    const float4* as4 = (const float4*)(a_src + h * C);
    const float4* ad4 = (const float4*)(a_dst + h * C);
    float ss = 0.f, dd = 0.f;
    for (int c = lane; c < C4; c += 32) {
        float4 v = row[c], a = as4[c], b = ad4[c];
        ss += v.x * a.x + v.y * a.y + v.z * a.z + v.w * a.w;
        dd += v.x * b.x + v.y * b.y + v.z * b.z + v.w * b.w;
    }
#pragma unroll
    for (int o = 16; o; o >>= 1) {
        ss += __shfl_xor_sync(0xffffffffu, ss, o);
        dd += __shfl_xor_sync(0xffffffffu, dd, o);
    }
    if (lane == 0) { s[w] = ss; d[w] = dd; }
}

// ---- aggregation: warp per (node,head), online softmax, float4 gather ----
template <int NCH, bool GUARD>
__global__ void k_agg(const float* __restrict__ xp, const float* __restrict__ s,
                      const float* __restrict__ dl, const float* __restrict__ bias,
                      float* __restrict__ out, int n, int H, int C, int ldxp, int ldout)
{
    int w = (blockIdx.x * blockDim.x + threadIdx.x) >> 5;
    int lane = threadIdx.x & 31;
    if (w >= n * H) return;
    int node = w / H, h = w - node * H;
    int C4 = C >> 2;
    float m = NEG_INF, z = 0.f;
    float4 acc[NCH];
#pragma unroll
    for (int r = 0; r < NCH; r++) acc[r] = make_float4(0.f, 0.f, 0.f, 0.f);
    float dn = dl[w];
    int beg = g_off[node], end = g_off[node + 1];
    for (int idx = beg; idx < end; idx++) {
        int src = g_csr[idx];
        float e = s[src * H + h] + dn;
        e = (e > 0.f) ? e : NEG_SLOPE * e;
        float mn = fmaxf(m, e);
        float scale = __expf(m - mn);       // m=-inf first edge -> 0
        float p = __expf(e - mn);
        z = z * scale + p;
        const float4* row = (const float4*)(xp + (size_t)src * ldxp + h * C);
#pragma unroll
        for (int r = 0; r < NCH; r++) {
            int ch = lane + r * 32;
            float4 v = (!GUARD || ch < C4) ? row[ch] : make_float4(0.f, 0.f, 0.f, 0.f);
            acc[r].x = acc[r].x * scale + p * v.x;
            acc[r].y = acc[r].y * scale + p * v.y;
            acc[r].z = acc[r].z * scale + p * v.z;
            acc[r].w = acc[r].w * scale + p * v.w;
        }
        m = mn;
    }
    float inv = 1.f / z;
    const float4* brow = (const float4*)(bias + h * C);
    float4* orow = (float4*)(out + (size_t)node * ldout + h * C);
#pragma unroll
    for (int r = 0; r < NCH; r++) {
        int ch = lane + r * 32;
        if (!GUARD || ch < C4) {
            float4 bv = brow[ch];
            float4 o;
            o.x = acc[r].x * inv + bv.x;
            o.y = acc[r].y * inv + bv.y;
            o.z = acc[r].z * inv + bv.z;
            o.w = acc[r].w * inv + bv.w;
            orow[ch] = o;
        }
    }
}

// ---------------- batch norm + ELU ----------------
__global__ void k_bn_zero() {
    int i = blockIdx.x * blockDim.x + threadIdx.x;
    if (i < HCOL) { g_bnsum[i] = 0.f; g_bnsq[i] = 0.f; }
}

__global__ __launch_bounds__(256) void k_bn_stats(const float* __restrict__ x, int n) {
    int tid = threadIdx.x;                  // owns cols tid, tid+256
    int r0 = blockIdx.x * 64;
    int r1 = min(r0 + 64, n);
    float s0 = 0.f, s1 = 0.f, q0 = 0.f, q1 = 0.f;
    for (int r = r0; r < r1; r++) {
        float v0 = x[(size_t)r * HCOL + tid];
        float v1 = x[(size_t)r * HCOL + tid + 256];
        s0 += v0; q0 += v0 * v0;
        s1 += v1; q1 += v1 * v1;
    }
    atomicAdd(&g_bnsum[tid],       s0);
    atomicAdd(&g_bnsq [tid],       q0);
    atomicAdd(&g_bnsum[tid + 256], s1);
    atomicAdd(&g_bnsq [tid + 256], q1);
}

__global__ void k_bn_finalize(const float* __restrict__ gamma, const float* __restrict__ beta, int n) {
    int c = blockIdx.x * blockDim.x + threadIdx.x;
    if (c >= HCOL) return;
    float mu = g_bnsum[c] / (float)n;
    float var = g_bnsq[c] / (float)n - mu * mu;
    float sc = gamma[c] * rsqrtf(var + BN_EPS);
    g_bnscale[c] = sc;
    g_bnshift[c] = beta[c] - mu * sc;
}

__global__ void k_bn_apply_elu(float* __restrict__ x, int n) {
    int i = blockIdx.x * blockDim.x + threadIdx.x;
    if (i >= n * HCOL) return;
    int c = i & (HCOL - 1);
    float v = x[i] * g_bnscale[c] + g_bnshift[c];
    x[i] = (v > 0.f) ? v : expm1f(v);
}

// ---------------- launch ----------------
extern "C" void kernel_launch(void* const* d_in, const int* in_sizes, int n_in,
                              void* d_out, int out_size)
{
    const float* x      = (const float*)d_in[0];
    const int*   ei     = (const int*)  d_in[1];
    const float* W1     = (const float*)d_in[2];
    const float* a_src1 = (const float*)d_in[3];
    const float* a_dst1 = (const float*)d_in[4];
    const float* b1     = (const float*)d_in[5];
    const float* g1     = (const float*)d_in[6];
    const float* be1    = (const float*)d_in[7];
    const float* W2     = (const float*)d_in[8];
    const float* a_src2 = (const float*)d_in[9];
    const float* a_dst2 = (const float*)d_in[10];
    const float* b2     = (const float*)d_in[11];
    const float* g2     = (const float*)d_in[12];
    const float* be2    = (const float*)d_in[13];
    const float* W3     = (const float*)d_in[14];
    const float* a_src3 = (const float*)d_in[15];
    const float* a_dst3 = (const float*)d_in[16];
    const float* b3     = (const float*)d_in[17];
    float* out = (float*)d_out;

    float *xp, *h, *s, *d;
    cudaGetSymbolAddress((void**)&xp, g_xp);
    cudaGetSymbolAddress((void**)&h,  g_h);
    cudaGetSymbolAddress((void**)&s,  g_s);
    cudaGetSymbolAddress((void**)&d,  g_d);

    static int smem_set = 0;
    if (!smem_set) {
        cudaFuncSetAttribute(k_gemm_tf32, cudaFuncAttributeMaxDynamicSharedMemorySize, SMEM_GEMM);
        smem_set = 1;
    }

    const int n = NNODES;

    // CSR build
    k_init_deg<<<(n + 255) / 256, 256>>>();
    k_hist<<<(NEDGES + 255) / 256, 256>>>(ei);
    k_scan<<<1, 1024>>>();
    k_scatter<<<(NEDGES + n + 255) / 256, 256>>>(ei);

    dim3 gemmGrid(4, (n + 127) / 128);
    int warpBlocks12 = (n * H12 * 32 + 255) / 256;   // warp per (node,head)
    int warpBlocks3  = (n * 32 + 255) / 256;

    // ---- layer 1 ----
    k_gemm_tf32<<<gemmGrid, 256, SMEM_GEMM>>>(x, W1, xp, n, 1280, HCOL, HCOL);
    k_logits<<<warpBlocks12, 256>>>(xp, a_src1, a_dst1, s, d, n, H12, C12, HCOL);
    k_agg<1, false><<<warpBlocks12, 256>>>(xp, s, d, b1, h, n, H12, C12, HCOL, HCOL);
    k_bn_zero<<<2, 256>>>();
    k_bn_stats<<<(n + 63) / 64, 256>>>(h, n);
    k_bn_finalize<<<2, 256>>>(g1, be1, n);
    k_bn_apply_elu<<<(n * HCOL + 255) / 256, 256>>>(h, n);

    // ---- layer 2 ----
    k_gemm_tf32<<<gemmGrid, 256, SMEM_GEMM>>>(h, W2, xp, n, HCOL, HCOL, HCOL);
    k_logits<<<warpBlocks12, 256>>>(xp, a_src2, a_dst2, s, d, n, H12, C12, HCOL);
    k_agg<1, false><<<warpBlocks12, 256>>>(xp, s, d, b2, h, n, H12, C12, HCOL, HCOL);
    k_bn_zero<<<2, 256>>>();
    k_bn_stats<<<(n + 63) / 64, 256>>>(h, n);
    k_bn_finalize<<<2, 256>>>(g2, be2, n);
    k_bn_apply_elu<<<(n * HCOL + 255) / 256, 256>>>(h, n);

    // ---- layer 3 (H=1, C=500, mean over 1 head == identity) ----
    k_gemm_tf32<<<gemmGrid, 256, SMEM_GEMM>>>(h, W3, xp, n, HCOL, C3, C3);
    k_logits<<<warpBlocks3, 256>>>(xp, a_src3, a_dst3, s, d, n, 1, C3, C3);
    k_agg<4, true><<<warpBlocks3, 256>>>(xp, s, d, b3, out, n, 1, C3, C3, C3);
}

// round 12
// speedup vs baseline: 2.1946x; 1.0065x over previous
#include <cuda_runtime.h>
#include <math.h>
#include <stdint.h>

#define NNODES 10000
#define NEDGES 320000
#define ETOT   (NNODES + NEDGES)
#define HCOL   512          // HID*HEADS
#define H12    4
#define C12    128
#define C3     500
#define BN_EPS 1e-5f
#define NEG_SLOPE 0.2f

#define NEG_INF __int_as_float(0xff800000)

// ---------------- scratch (static __device__, no allocation) ----------------
__device__ float g_xp[NNODES * HCOL];      // transformed features (ld=500 for L3)
__device__ float g_h [NNODES * HCOL];      // aggregated / activated features
__device__ float g_s [NNODES * H12];
__device__ float g_d [NNODES * H12];
__device__ float g_alpha[ETOT * H12];      // normalized attention per (csr pos, head)
__device__ int   g_deg[NNODES];
__device__ int   g_off[NNODES + 1];
__device__ int   g_cur[NNODES];
__device__ int   g_csr[ETOT];
__device__ float g_bnsum[HCOL], g_bnsq[HCOL], g_bnscale[HCOL], g_bnshift[HCOL];

// ---------------- CSR build ----------------
__global__ void k_init_deg() {
    int i = blockIdx.x * blockDim.x + threadIdx.x;
    if (i < NNODES) g_deg[i] = 1;          // self loop
}

__global__ void k_hist(const int* __restrict__ ei) {
    int i = blockIdx.x * blockDim.x + threadIdx.x;
    if (i < NEDGES) atomicAdd(&g_deg[ei[NEDGES + i]], 1);   // dst row
}

__global__ void k_scan() {                  // single block, 1024 threads
    __shared__ int sm[1024];
    __shared__ int carry;
    int t = threadIdx.x;
    if (t == 0) carry = 0;
    __syncthreads();
    for (int base = 0; base < NNODES; base += 1024) {
        int i = base + t;
        int v = (i < NNODES) ? g_deg[i] : 0;
        sm[t] = v; __syncthreads();
        for (int off = 1; off < 1024; off <<= 1) {
            int tv = (t >= off) ? sm[t - off] : 0;
            __syncthreads();
            sm[t] += tv;
            __syncthreads();
        }
        int excl = sm[t] - v;
        if (i < NNODES) { g_off[i] = carry + excl; g_cur[i] = carry + excl; }
        __syncthreads();
        if (t == 1023) carry += sm[1023];
        __syncthreads();
    }
    if (t == 0) g_off[NNODES] = carry;      // = ETOT
}

__global__ void k_scatter(const int* __restrict__ ei) {
    int i = blockIdx.x * blockDim.x + threadIdx.x;
    if (i < NEDGES) {
        int s = ei[i], dst = ei[NEDGES + i];
        int p = atomicAdd(&g_cur[dst], 1);
        g_csr[p] = s;
    } else if (i < NEDGES + NNODES) {
        int nid = i - NEDGES;               // self loop
        int p = atomicAdd(&g_cur[nid], 1);
        g_csr[p] = nid;
    }
}

// ---------------- TF32 tensor-core GEMM, cp.async 3-stage pipeline ----------------
#define AS_STRIDE 36
#define BS_STRIDE 136
#define A_TILE (128 * AS_STRIDE)
#define B_TILE (32 * BS_STRIDE)
#define NSTAGE 3
#define SMEM_GEMM (NSTAGE * (A_TILE + B_TILE) * 4)

__device__ __forceinline__ uint32_t f2tf32(float x) {
    uint32_t r;
    asm("cvt.rna.tf32.f32 %0, %1;" : "=r"(r) : "f"(x));
    return r;
}

__device__ __forceinline__ void mma_tf32(float* c, const uint32_t* a, const uint32_t* b) {
    asm volatile(
        "mma.sync.aligned.m16n8k8.row.col.f32.tf32.tf32.f32 "
        "{%0,%1,%2,%3}, {%4,%5,%6,%7}, {%8,%9}, {%0,%1,%2,%3};"
        : "+f"(c[0]), "+f"(c[1]), "+f"(c[2]), "+f"(c[3])
        : "r"(a[0]), "r"(a[1]), "r"(a[2]), "r"(a[3]), "r"(b[0]), "r"(b[1]));
}

__device__ __forceinline__ void cp16(float* dst, const float* src) {
    uint32_t d = (uint32_t)__cvta_generic_to_shared(dst);
    asm volatile("cp.async.cg.shared.global [%0], [%1], 16;"
                 :: "r"(d), "l"(src) : "memory");
}

__device__ __forceinline__ void load_tile(
    const float* __restrict__ A, const float* __restrict__ B,
    int M, int K, int Ncols, int row0, int col0, int k0,
    float* As_st, float* Bs_st, int tid)
{
#pragma unroll
    for (int it = 0; it < 4; it++) {
        int e = tid + it * 256;             // 0..1023
        int r = e >> 3;                     // 0..127
        int kc = (e & 7) * 4;
        int gr = row0 + r;
        if (gr >= M) gr = M - 1;            // clamp: garbage rows never stored
        cp16(As_st + r * AS_STRIDE + kc, A + (size_t)gr * K + k0 + kc);
    }
#pragma unroll
    for (int it = 0; it < 4; it++) {
        int e = tid + it * 256;
        int kr = e >> 5;                    // 0..31
        int nc = (e & 31) * 4;
        int gc = col0 + nc;
        if (gc >= Ncols) gc = Ncols - 4;    // clamp: garbage cols never stored
        cp16(Bs_st + kr * BS_STRIDE + nc, B + (size_t)(k0 + kr) * Ncols + gc);
    }
}

__global__ __launch_bounds__(256) void k_gemm_tf32(
    const float* __restrict__ A, const float* __restrict__ B, float* __restrict__ C,
    int M, int K, int Ncols, int ldc)
{
    extern __shared__ float smp[];
    float* As = smp;                        // [NSTAGE][A_TILE]
    float* Bs = smp + NSTAGE * A_TILE;      // [NSTAGE][B_TILE]

    int tid  = threadIdx.x;
    int warp = tid >> 5, lane = tid & 31;
    int lr = lane >> 2, lc = lane & 3;
    int row0 = blockIdx.y * 128, col0 = blockIdx.x * 128;
    int wm = (warp & 3) * 32;               // warp m-offset
    int wn = (warp >> 2) * 64;              // warp n-offset

    float acc[2][8][4];
#pragma unroll
    for (int i = 0; i < 2; i++)
#pragma unroll
        for (int j = 0; j < 8; j++)
#pragma unroll
            for (int r = 0; r < 4; r++) acc[i][j][r] = 0.f;

    int T = K >> 5;                         // K % 32 == 0 always

    load_tile(A, B, M, K, Ncols, row0, col0, 0, As, Bs, tid);
    asm volatile("cp.async.commit_group;" ::: "memory");
    load_tile(A, B, M, K, Ncols, row0, col0, 32, As + A_TILE, Bs + B_TILE, tid);
    asm volatile("cp.async.commit_group;" ::: "memory");

    for (int kt = 0; kt < T; kt++) {
        if (kt + 2 < T) {
            int st = (kt + 2) % NSTAGE;
            load_tile(A, B, M, K, Ncols, row0, col0, (kt + 2) * 32,
                      As + st * A_TILE, Bs + st * B_TILE, tid);
        }
        asm volatile("cp.async.commit_group;" ::: "memory");
        asm volatile("cp.async.wait_group 2;" ::: "memory");
        __syncthreads();

        const float* a_s = As + (kt % NSTAGE) * A_TILE;
        const float* b_s = Bs + (kt % NSTAGE) * B_TILE;

#pragma unroll
        for (int kk = 0; kk < 32; kk += 8) {
            uint32_t af[2][4], bf[8][2];
#pragma unroll
            for (int mi = 0; mi < 2; mi++) {
                int m = wm + mi * 16;
                af[mi][0] = f2tf32(a_s[(m + lr    ) * AS_STRIDE + kk + lc    ]);
                af[mi][1] = f2tf32(a_s[(m + lr + 8) * AS_STRIDE + kk + lc    ]);
                af[mi][2] = f2tf32(a_s[(m + lr    ) * AS_STRIDE + kk + lc + 4]);
                af[mi][3] = f2tf32(a_s[(m + lr + 8) * AS_STRIDE + kk + lc + 4]);
            }
#pragma unroll
            for (int ni = 0; ni < 8; ni++) {
                int nn = wn + ni * 8;
                bf[ni][0] = f2tf32(b_s[(kk + lc    ) * BS_STRIDE + nn + lr]);
                bf[ni][1] = f2tf32(b_s[(kk + lc + 4) * BS_STRIDE + nn + lr]);
            }
#pragma unroll
            for (int mi = 0; mi < 2; mi++)
#pragma unroll
                for (int ni = 0; ni < 8; ni++)
                    mma_tf32(acc[mi][ni], af[mi], bf[ni]);
        }
        __syncthreads();
    }

    // --- store C (Ncols % 4 == 0 -> float2 pairs stay in-bounds together) ---
#pragma unroll
    for (int mi = 0; mi < 2; mi++) {
#pragma unroll
        for (int ni = 0; ni < 8; ni++) {
            int colb = col0 + wn + ni * 8 + lc * 2;
            if (colb >= Ncols) continue;
#pragma unroll
            for (int hh = 0; hh < 2; hh++) {
                int r = row0 + wm + mi * 16 + lr + hh * 8;
                if (r < M) {
                    float2 v = make_float2(acc[mi][ni][hh * 2], acc[mi][ni][hh * 2 + 1]);
                    *(float2*)(C + (size_t)r * ldc + colb) = v;
                }
            }
        }
    }
}

// ---------------- per-(node,head) attention logits (float4) ----------------
__global__ void k_logits(const float* __restrict__ xp, const float* __restrict__ a_src,
                         const float* __restrict__ a_dst, float* __restrict__ s,
                         float* __restrict__ d, int n, int H, int C, int ld)
{
    int w = (blockIdx.x * blockDim.x + threadIdx.x) >> 5;
    int lane = threadIdx.x & 31;
    if (w >= n * H) return;
    int node = w / H, h = w - node * H;
    int C4 = C >> 2;                        // C % 4 == 0 (128, 500)
    const float4* row = (const float4*)(xp + (size_t)node * ld + h * C);
    const float4* as4 = (const float4*)(a_src + h * C);
    const float4* ad4 = (const float4*)(a_dst + h * C);
    float ss = 0.f, dd = 0.f;
    for (int c = lane; c < C4; c += 32) {
        float4 v = row[c], a = as4[c], b = ad4[c];
        ss += v.x * a.x + v.y * a.y + v.z * a.z + v.w * a.w;
        dd += v.x * b.x + v.y * b.y + v.z * b.z + v.w * b.w;
    }
#pragma unroll
    for (int o = 16; o; o >>= 1) {
        ss += __shfl_xor_sync(0xffffffffu, ss, o);
        dd += __shfl_xor_sync(0xffffffffu, dd, o);
    }
    if (lane == 0) { s[w] = ss; d[w] = dd; }
}

// ---- pass 1: normalized attention weights, warp per (node,head), lanes over edges ----
__global__ void k_alpha(const float* __restrict__ s, const float* __restrict__ dl,
                        float* __restrict__ alpha, int n, int H)
{
    int w = (blockIdx.x * blockDim.x + threadIdx.x) >> 5;
    int lane = threadIdx.x & 31;
    if (w >= n * H) return;
    int node = w / H, h = w - node * H;
    float dn = dl[w];
    int beg = g_off[node], end = g_off[node + 1];

    float m = NEG_INF;
    for (int idx = beg + lane; idx < end; idx += 32) {
        int src = g_csr[idx];
        float e = s[src * H + h] + dn;
        e = (e > 0.f) ? e : NEG_SLOPE * e;
        m = fmaxf(m, e);
    }
#pragma unroll
    for (int o = 16; o; o >>= 1) m = fmaxf(m, __shfl_xor_sync(0xffffffffu, m, o));

    float zz = 0.f;
    for (int idx = beg + lane; idx < end; idx += 32) {
        int src = g_csr[idx];
        float e = s[src * H + h] + dn;
        e = (e > 0.f) ? e : NEG_SLOPE * e;
        float p = __expf(e - m);
        alpha[(size_t)idx * H + h] = p;
        zz += p;
    }
#pragma unroll
    for (int o = 16; o; o >>= 1) zz += __shfl_xor_sync(0xffffffffu, zz, o);

    float inv = 1.f / zz;
    for (int idx = beg + lane; idx < end; idx += 32)
        alpha[(size_t)idx * H + h] *= inv;
}

// ---- pass 2: pure weighted gather, warp per (node,head), float4 per lane ----
template <int NCH, bool GUARD>
__global__ void k_agg2(const float* __restrict__ xp, const float* __restrict__ alpha,
                       const float* __restrict__ bias, float* __restrict__ out,
                       int n, int H, int C, int ldxp, int ldout)
{
    int w = (blockIdx.x * blockDim.x + threadIdx.x) >> 5;
    int lane = threadIdx.x & 31;
    if (w >= n * H) return;
    int node = w / H, h = w - node * H;
    int C4 = C >> 2;
    float4 acc[NCH];
#pragma unroll
    for (int r = 0; r < NCH; r++) acc[r] = make_float4(0.f, 0.f, 0.f, 0.f);
    int beg = g_off[node], end = g_off[node + 1];

#pragma unroll 2
    for (int idx = beg; idx < end; idx++) {
        int src = g_csr[idx];
        float a = alpha[(size_t)idx * H + h];
        const float4* row = (const float4*)(xp + (size_t)src * ldxp + h * C);
#pragma unroll
        for (int r = 0; r < NCH; r++) {
            int ch = lane + r * 32;
            float4 v = (!GUARD || ch < C4) ? row[ch] : make_float4(0.f, 0.f, 0.f, 0.f);
            acc[r].x += a * v.x;
            acc[r].y += a * v.y;
            acc[r].z += a * v.z;
            acc[r].w += a * v.w;
        }
    }

    const float4* brow = (const float4*)(bias + h * C);
    float4* orow = (float4*)(out + (size_t)node * ldout + h * C);
#pragma unroll
    for (int r = 0; r < NCH; r++) {
        int ch = lane + r * 32;
        if (!GUARD || ch < C4) {
            float4 bv = brow[ch];
            float4 o;
            o.x = acc[r].x + bv.x;
            o.y = acc[r].y + bv.y;
            o.z = acc[r].z + bv.z;
            o.w = acc[r].w + bv.w;
            orow[ch] = o;
        }
    }
}

// ---------------- batch norm + ELU ----------------
__global__ void k_bn_zero() {
    int i = blockIdx.x * blockDim.x + threadIdx.x;
    if (i < HCOL) { g_bnsum[i] = 0.f; g_bnsq[i] = 0.f; }
}

__global__ __launch_bounds__(256) void k_bn_stats(const float* __restrict__ x, int n) {
    int tid = threadIdx.x;                  // owns cols tid, tid+256
    int r0 = blockIdx.x * 64;
    int r1 = min(r0 + 64, n);
    float s0 = 0.f, s1 = 0.f, q0 = 0.f, q1 = 0.f;
    for (int r = r0; r < r1; r++) {
        float v0 = x[(size_t)r * HCOL + tid];
        float v1 = x[(size_t)r * HCOL + tid + 256];
        s0 += v0; q0 += v0 * v0;
        s1 += v1; q1 += v1 * v1;
    }
    atomicAdd(&g_bnsum[tid],       s0);
    atomicAdd(&g_bnsq [tid],       q0);
    atomicAdd(&g_bnsum[tid + 256], s1);
    atomicAdd(&g_bnsq [tid + 256], q1);
}

__global__ void k_bn_finalize(const float* __restrict__ gamma, const float* __restrict__ beta, int n) {
    int c = blockIdx.x * blockDim.x + threadIdx.x;
    if (c >= HCOL) return;
    float mu = g_bnsum[c] / (float)n;
    float var = g_bnsq[c] / (float)n - mu * mu;
    float sc = gamma[c] * rsqrtf(var + BN_EPS);
    g_bnscale[c] = sc;
    g_bnshift[c] = beta[c] - mu * sc;
}

__global__ void k_bn_apply_elu(float* __restrict__ x, int n) {
    int i = blockIdx.x * blockDim.x + threadIdx.x;
    if (i >= n * HCOL) return;
    int c = i & (HCOL - 1);
    float v = x[i] * g_bnscale[c] + g_bnshift[c];
    x[i] = (v > 0.f) ? v : expm1f(v);
}

// ---------------- launch ----------------
extern "C" void kernel_launch(void* const* d_in, const int* in_sizes, int n_in,
                              void* d_out, int out_size)
{
    const float* x      = (const float*)d_in[0];
    const int*   ei     = (const int*)  d_in[1];
    const float* W1     = (const float*)d_in[2];
    const float* a_src1 = (const float*)d_in[3];
    const float* a_dst1 = (const float*)d_in[4];
    const float* b1     = (const float*)d_in[5];
    const float* g1     = (const float*)d_in[6];
    const float* be1    = (const float*)d_in[7];
    const float* W2     = (const float*)d_in[8];
    const float* a_src2 = (const float*)d_in[9];
    const float* a_dst2 = (const float*)d_in[10];
    const float* b2     = (const float*)d_in[11];
    const float* g2     = (const float*)d_in[12];
    const float* be2    = (const float*)d_in[13];
    const float* W3     = (const float*)d_in[14];
    const float* a_src3 = (const float*)d_in[15];
    const float* a_dst3 = (const float*)d_in[16];
    const float* b3     = (const float*)d_in[17];
    float* out = (float*)d_out;

    float *xp, *h, *s, *d, *al;
    cudaGetSymbolAddress((void**)&xp, g_xp);
    cudaGetSymbolAddress((void**)&h,  g_h);
    cudaGetSymbolAddress((void**)&s,  g_s);
    cudaGetSymbolAddress((void**)&d,  g_d);
    cudaGetSymbolAddress((void**)&al, g_alpha);

    static int smem_set = 0;
    if (!smem_set) {
        cudaFuncSetAttribute(k_gemm_tf32, cudaFuncAttributeMaxDynamicSharedMemorySize, SMEM_GEMM);
        smem_set = 1;
    }

    const int n = NNODES;

    // CSR build
    k_init_deg<<<(n + 255) / 256, 256>>>();
    k_hist<<<(NEDGES + 255) / 256, 256>>>(ei);
    k_scan<<<1, 1024>>>();
    k_scatter<<<(NEDGES + n + 255) / 256, 256>>>(ei);

    dim3 gemmGrid(4, (n + 127) / 128);
    int warpBlocks12 = (n * H12 * 32 + 255) / 256;   // warp per (node,head)
    int warpBlocks3  = (n * 32 + 255) / 256;

    // ---- layer 1 ----
    k_gemm_tf32<<<gemmGrid, 256, SMEM_GEMM>>>(x, W1, xp, n, 1280, HCOL, HCOL);
    k_logits<<<warpBlocks12, 256>>>(xp, a_src1, a_dst1, s, d, n, H12, C12, HCOL);
    k_alpha<<<warpBlocks12, 256>>>(s, d, al, n, H12);
    k_agg2<1, false><<<warpBlocks12, 256>>>(xp, al, b1, h, n, H12, C12, HCOL, HCOL);
    k_bn_zero<<<2, 256>>>();
    k_bn_stats<<<(n + 63) / 64, 256>>>(h, n);
    k_bn_finalize<<<2, 256>>>(g1, be1, n);
    k_bn_apply_elu<<<(n * HCOL + 255) / 256, 256>>>(h, n);

    // ---- layer 2 ----
    k_gemm_tf32<<<gemmGrid, 256, SMEM_GEMM>>>(h, W2, xp, n, HCOL, HCOL, HCOL);
    k_logits<<<warpBlocks12, 256>>>(xp, a_src2, a_dst2, s, d, n, H12, C12, HCOL);
    k_alpha<<<warpBlocks12, 256>>>(s, d, al, n, H12);
    k_agg2<1, false><<<warpBlocks12, 256>>>(xp, al, b2, h, n, H12, C12, HCOL, HCOL);
    k_bn_zero<<<2, 256>>>();
    k_bn_stats<<<(n + 63) / 64, 256>>>(h, n);
    k_bn_finalize<<<2, 256>>>(g2, be2, n);
    k_bn_apply_elu<<<(n * HCOL + 255) / 256, 256>>>(h, n);

    // ---- layer 3 (H=1, C=500, mean over 1 head == identity) ----
    k_gemm_tf32<<<gemmGrid, 256, SMEM_GEMM>>>(h, W3, xp, n, HCOL, C3, C3);
    k_logits<<<warpBlocks3, 256>>>(xp, a_src3, a_dst3, s, d, n, 1, C3, C3);
    k_alpha<<<warpBlocks3, 256>>>(s, d, al, n, 1);
    k_agg2<4, true><<<warpBlocks3, 256>>>(xp, al, b3, out, n, 1, C3, C3, C3);
}

// round 13
// speedup vs baseline: 2.3871x; 1.0877x over previous
#include <cuda_runtime.h>
#include <math.h>
#include <stdint.h>

#define NNODES 10000
#define NEDGES 320000
#define ETOT   (NNODES + NEDGES)
#define HCOL   512          // HID*HEADS
#define H12    4
#define C12    128
#define C3     500
#define IN1    1280
#define BN_EPS 1e-5f
#define NEG_SLOPE 0.2f

#define NEG_INF __int_as_float(0xff800000)

// ---------------- scratch (static __device__, no allocation) ----------------
__device__ float g_xp[NNODES * HCOL];      // transformed features (ld=500 for L3)
__device__ float g_h [NNODES * HCOL];      // aggregated / activated features
__device__ float g_s [NNODES * H12];
__device__ float g_d [NNODES * H12];
__device__ float g_alpha[ETOT * H12];      // normalized attention per (csr pos, head)
__device__ float g_xr[NNODES * IN1];       // tf32-rounded x
__device__ float g_wr[IN1 * HCOL + HCOL * HCOL + HCOL * C3];  // tf32-rounded W1|W2|W3
__device__ int   g_deg[NNODES];
__device__ int   g_off[NNODES + 1];
__device__ int   g_cur[NNODES];
__device__ int   g_csr[ETOT];
__device__ float g_bnsum[HCOL], g_bnsq[HCOL], g_bnscale[HCOL], g_bnshift[HCOL];

#define W2R_OFF (IN1 * HCOL)
#define W3R_OFF (IN1 * HCOL + HCOL * HCOL)

__device__ __forceinline__ uint32_t f2tf32(float x) {
    uint32_t r;
    asm("cvt.rna.tf32.f32 %0, %1;" : "=r"(r) : "f"(x));
    return r;
}

// ---------------- tf32 pre-rounding (float4) ----------------
__global__ void k_round_tf32(const float* __restrict__ in, float* __restrict__ out, int n4) {
    int i = blockIdx.x * blockDim.x + threadIdx.x;
    if (i >= n4) return;
    float4 v = ((const float4*)in)[i];
    float4 o;
    o.x = __uint_as_float(f2tf32(v.x));
    o.y = __uint_as_float(f2tf32(v.y));
    o.z = __uint_as_float(f2tf32(v.z));
    o.w = __uint_as_float(f2tf32(v.w));
    ((float4*)out)[i] = o;
}

// ---------------- CSR build ----------------
__global__ void k_init_deg() {
    int i = blockIdx.x * blockDim.x + threadIdx.x;
    if (i < NNODES) g_deg[i] = 1;          // self loop
}

__global__ void k_hist(const int* __restrict__ ei) {
    int i = blockIdx.x * blockDim.x + threadIdx.x;
    if (i < NEDGES) atomicAdd(&g_deg[ei[NEDGES + i]], 1);   // dst row
}

__global__ void k_scan() {                  // single block, 1024 threads
    __shared__ int sm[1024];
    __shared__ int carry;
    int t = threadIdx.x;
    if (t == 0) carry = 0;
    __syncthreads();
    for (int base = 0; base < NNODES; base += 1024) {
        int i = base + t;
        int v = (i < NNODES) ? g_deg[i] : 0;
        sm[t] = v; __syncthreads();
        for (int off = 1; off < 1024; off <<= 1) {
            int tv = (t >= off) ? sm[t - off] : 0;
            __syncthreads();
            sm[t] += tv;
            __syncthreads();
        }
        int excl = sm[t] - v;
        if (i < NNODES) { g_off[i] = carry + excl; g_cur[i] = carry + excl; }
        __syncthreads();
        if (t == 1023) carry += sm[1023];
        __syncthreads();
    }
    if (t == 0) g_off[NNODES] = carry;      // = ETOT
}

__global__ void k_scatter(const int* __restrict__ ei) {
    int i = blockIdx.x * blockDim.x + threadIdx.x;
    if (i < NEDGES) {
        int s = ei[i], dst = ei[NEDGES + i];
        int p = atomicAdd(&g_cur[dst], 1);
        g_csr[p] = s;
    } else if (i < NEDGES + NNODES) {
        int nid = i - NEDGES;               // self loop
        int p = atomicAdd(&g_cur[nid], 1);
        g_csr[p] = nid;
    }
}

// ---------------- TF32 tensor-core GEMM, cp.async 3-stage pipeline ----------------
// Inputs pre-rounded to tf32 values -> no cvt in the inner loop.
#define AS_STRIDE 36
#define BS_STRIDE 136
#define A_TILE (128 * AS_STRIDE)
#define B_TILE (32 * BS_STRIDE)
#define NSTAGE 3
#define SMEM_GEMM (NSTAGE * (A_TILE + B_TILE) * 4)

__device__ __forceinline__ void mma_tf32(float* c, const uint32_t* a, const uint32_t* b) {
    asm volatile(
        "mma.sync.aligned.m16n8k8.row.col.f32.tf32.tf32.f32 "
        "{%0,%1,%2,%3}, {%4,%5,%6,%7}, {%8,%9}, {%0,%1,%2,%3};"
        : "+f"(c[0]), "+f"(c[1]), "+f"(c[2]), "+f"(c[3])
        : "r"(a[0]), "r"(a[1]), "r"(a[2]), "r"(a[3]), "r"(b[0]), "r"(b[1]));
}

__device__ __forceinline__ void cp16(float* dst, const float* src) {
    uint32_t d = (uint32_t)__cvta_generic_to_shared(dst);
    asm volatile("cp.async.cg.shared.global [%0], [%1], 16;"
                 :: "r"(d), "l"(src) : "memory");
}

__device__ __forceinline__ void load_tile(
    const float* __restrict__ A, const float* __restrict__ B,
    int M, int K, int Ncols, int row0, int col0, int k0,
    float* As_st, float* Bs_st, int tid)
{
#pragma unroll
    for (int it = 0; it < 4; it++) {
        int e = tid + it * 256;             // 0..1023
        int r = e >> 3;                     // 0..127
        int kc = (e & 7) * 4;
        int gr = row0 + r;
        if (gr >= M) gr = M - 1;            // clamp: garbage rows never stored
        cp16(As_st + r * AS_STRIDE + kc, A + (size_t)gr * K + k0 + kc);
    }
#pragma unroll
    for (int it = 0; it < 4; it++) {
        int e = tid + it * 256;
        int kr = e >> 5;                    // 0..31
        int nc = (e & 31) * 4;
        int gc = col0 + nc;
        if (gc >= Ncols) gc = Ncols - 4;    // clamp: garbage cols never stored
        cp16(Bs_st + kr * BS_STRIDE + nc, B + (size_t)(k0 + kr) * Ncols + gc);
    }
}

__global__ __launch_bounds__(256) void k_gemm_tf32(
    const float* __restrict__ A, const float* __restrict__ B, float* __restrict__ C,
    int M, int K, int Ncols, int ldc)
{
    extern __shared__ float smp[];
    float* As = smp;                        // [NSTAGE][A_TILE]
    float* Bs = smp + NSTAGE * A_TILE;      // [NSTAGE][B_TILE]

    int tid  = threadIdx.x;
    int warp = tid >> 5, lane = tid & 31;
    int lr = lane >> 2, lc = lane & 3;
    int row0 = blockIdx.y * 128, col0 = blockIdx.x * 128;
    int wm = (warp & 3) * 32;               // warp m-offset
    int wn = (warp >> 2) * 64;              // warp n-offset

    float acc[2][8][4];
#pragma unroll
    for (int i = 0; i < 2; i++)
#pragma unroll
        for (int j = 0; j < 8; j++)
#pragma unroll
            for (int r = 0; r < 4; r++) acc[i][j][r] = 0.f;

    int T = K >> 5;                         // K % 32 == 0 always

    load_tile(A, B, M, K, Ncols, row0, col0, 0, As, Bs, tid);
    asm volatile("cp.async.commit_group;" ::: "memory");
    load_tile(A, B, M, K, Ncols, row0, col0, 32, As + A_TILE, Bs + B_TILE, tid);
    asm volatile("cp.async.commit_group;" ::: "memory");

    for (int kt = 0; kt < T; kt++) {
        if (kt + 2 < T) {
            int st = (kt + 2) % NSTAGE;
            load_tile(A, B, M, K, Ncols, row0, col0, (kt + 2) * 32,
                      As + st * A_TILE, Bs + st * B_TILE, tid);
        }
        asm volatile("cp.async.commit_group;" ::: "memory");
        asm volatile("cp.async.wait_group 2;" ::: "memory");
        __syncthreads();

        const float* a_s = As + (kt % NSTAGE) * A_TILE;
        const float* b_s = Bs + (kt % NSTAGE) * B_TILE;

#pragma unroll
        for (int kk = 0; kk < 32; kk += 8) {
            uint32_t af[2][4], bf[8][2];
#pragma unroll
            for (int mi = 0; mi < 2; mi++) {
                int m = wm + mi * 16;
                af[mi][0] = __float_as_uint(a_s[(m + lr    ) * AS_STRIDE + kk + lc    ]);
                af[mi][1] = __float_as_uint(a_s[(m + lr + 8) * AS_STRIDE + kk + lc    ]);
                af[mi][2] = __float_as_uint(a_s[(m + lr    ) * AS_STRIDE + kk + lc + 4]);
                af[mi][3] = __float_as_uint(a_s[(m + lr + 8) * AS_STRIDE + kk + lc + 4]);
            }
#pragma unroll
            for (int ni = 0; ni < 8; ni++) {
                int nn = wn + ni * 8;
                bf[ni][0] = __float_as_uint(b_s[(kk + lc    ) * BS_STRIDE + nn + lr]);
                bf[ni][1] = __float_as_uint(b_s[(kk + lc + 4) * BS_STRIDE + nn + lr]);
            }
#pragma unroll
            for (int mi = 0; mi < 2; mi++)
#pragma unroll
                for (int ni = 0; ni < 8; ni++)
                    mma_tf32(acc[mi][ni], af[mi], bf[ni]);
        }
        __syncthreads();
    }

    // --- store C (Ncols % 4 == 0 -> float2 pairs stay in-bounds together) ---
#pragma unroll
    for (int mi = 0; mi < 2; mi++) {
#pragma unroll
        for (int ni = 0; ni < 8; ni++) {
            int colb = col0 + wn + ni * 8 + lc * 2;
            if (colb >= Ncols) continue;
#pragma unroll
            for (int hh = 0; hh < 2; hh++) {
                int r = row0 + wm + mi * 16 + lr + hh * 8;
                if (r < M) {
                    float2 v = make_float2(acc[mi][ni][hh * 2], acc[mi][ni][hh * 2 + 1]);
                    *(float2*)(C + (size_t)r * ldc + colb) = v;
                }
            }
        }
    }
}

// ---------------- per-(node,head) attention logits (float4) ----------------
__global__ void k_logits(const float* __restrict__ xp, const float* __restrict__ a_src,
                         const float* __restrict__ a_dst, float* __restrict__ s,
                         float* __restrict__ d, int n, int H, int C, int ld)
{
    int w = (blockIdx.x * blockDim.x + threadIdx.x) >> 5;
    int lane = threadIdx.x & 31;
    if (w >= n * H) return;
    int node = w / H, h = w - node * H;
    int C4 = C >> 2;                        // C % 4 == 0 (128, 500)
    const float4* row = (const float4*)(xp + (size_t)node * ld + h * C);
    const float4* as4 = (const float4*)(a_src + h * C);
    const float4* ad4 = (const float4*)(a_dst + h * C);
    float ss = 0.f, dd = 0.f;
    for (int c = lane; c < C4; c += 32) {
        float4 v = row[c], a = as4[c], b = ad4[c];
        ss += v.x * a.x + v.y * a.y + v.z * a.z + v.w * a.w;
        dd += v.x * b.x + v.y * b.y + v.z * b.z + v.w * b.w;
    }
#pragma unroll
    for (int o = 16; o; o >>= 1) {
        ss += __shfl_xor_sync(0xffffffffu, ss, o);
        dd += __shfl_xor_sync(0xffffffffu, dd, o);
    }
    if (lane == 0) { s[w] = ss; d[w] = dd; }
}

// ---- pass 1: normalized attention weights, warp per (node,head), lanes over edges ----
__global__ void k_alpha(const float* __restrict__ s, const float* __restrict__ dl,
                        float* __restrict__ alpha, int n, int H)
{
    int w = (blockIdx.x * blockDim.x + threadIdx.x) >> 5;
    int lane = threadIdx.x & 31;
    if (w >= n * H) return;
    int node = w / H, h = w - node * H;
    float dn = dl[w];
    int beg = g_off[node], end = g_off[node + 1];

    float m = NEG_INF;
    for (int idx = beg + lane; idx < end; idx += 32) {
        int src = g_csr[idx];
        float e = s[src * H + h] + dn;
        e = (e > 0.f) ? e : NEG_SLOPE * e;
        m = fmaxf(m, e);
    }
#pragma unroll
    for (int o = 16; o; o >>= 1) m = fmaxf(m, __shfl_xor_sync(0xffffffffu, m, o));

    float zz = 0.f;
    for (int idx = beg + lane; idx < end; idx += 32) {
        int src = g_csr[idx];
        float e = s[src * H + h] + dn;
        e = (e > 0.f) ? e : NEG_SLOPE * e;
        float p = __expf(e - m);
        alpha[(size_t)idx * H + h] = p;
        zz += p;
    }
#pragma unroll
    for (int o = 16; o; o >>= 1) zz += __shfl_xor_sync(0xffffffffu, zz, o);

    float inv = 1.f / zz;
    for (int idx = beg + lane; idx < end; idx += 32)
        alpha[(size_t)idx * H + h] *= inv;
}

// ---- pass 2: pure weighted gather, warp per (node,head), float4 per lane ----
template <int NCH, bool GUARD>
__global__ void k_agg2(const float* __restrict__ xp, const float* __restrict__ alpha,
                       const float* __restrict__ bias, float* __restrict__ out,
                       int n, int H, int C, int ldxp, int ldout)
{
    int w = (blockIdx.x * blockDim.x + threadIdx.x) >> 5;
    int lane = threadIdx.x & 31;
    if (w >= n * H) return;
    int node = w / H, h = w - node * H;
    int C4 = C >> 2;
    float4 acc[NCH];
#pragma unroll
    for (int r = 0; r < NCH; r++) acc[r] = make_float4(0.f, 0.f, 0.f, 0.f);
    int beg = g_off[node], end = g_off[node + 1];

#pragma unroll 2
    for (int idx = beg; idx < end; idx++) {
        int src = g_csr[idx];
        float a = alpha[(size_t)idx * H + h];
        const float4* row = (const float4*)(xp + (size_t)src * ldxp + h * C);
#pragma unroll
        for (int r = 0; r < NCH; r++) {
            int ch = lane + r * 32;
            float4 v = (!GUARD || ch < C4) ? row[ch] : make_float4(0.f, 0.f, 0.f, 0.f);
            acc[r].x += a * v.x;
            acc[r].y += a * v.y;
            acc[r].z += a * v.z;
            acc[r].w += a * v.w;
        }
    }

    const float4* brow = (const float4*)(bias + h * C);
    float4* orow = (float4*)(out + (size_t)node * ldout + h * C);
#pragma unroll
    for (int r = 0; r < NCH; r++) {
        int ch = lane + r * 32;
        if (!GUARD || ch < C4) {
            float4 bv = brow[ch];
            float4 o;
            o.x = acc[r].x + bv.x;
            o.y = acc[r].y + bv.y;
            o.z = acc[r].z + bv.z;
            o.w = acc[r].w + bv.w;
            orow[ch] = o;
        }
    }
}

// ---------------- batch norm + ELU ----------------
__global__ void k_bn_zero() {
    int i = blockIdx.x * blockDim.x + threadIdx.x;
    if (i < HCOL) { g_bnsum[i] = 0.f; g_bnsq[i] = 0.f; }
}

__global__ __launch_bounds__(256) void k_bn_stats(const float* __restrict__ x, int n) {
    int tid = threadIdx.x;                  // owns cols tid, tid+256
    int r0 = blockIdx.x * 64;
    int r1 = min(r0 + 64, n);
    float s0 = 0.f, s1 = 0.f, q0 = 0.f, q1 = 0.f;
    for (int r = r0; r < r1; r++) {
        float v0 = x[(size_t)r * HCOL + tid];
        float v1 = x[(size_t)r * HCOL + tid + 256];
        s0 += v0; q0 += v0 * v0;
        s1 += v1; q1 += v1 * v1;
    }
    atomicAdd(&g_bnsum[tid],       s0);
    atomicAdd(&g_bnsq [tid],       q0);
    atomicAdd(&g_bnsum[tid + 256], s1);
    atomicAdd(&g_bnsq [tid + 256], q1);
}

__global__ void k_bn_finalize(const float* __restrict__ gamma, const float* __restrict__ beta, int n) {
    int c = blockIdx.x * blockDim.x + threadIdx.x;
    if (c >= HCOL) return;
    float mu = g_bnsum[c] / (float)n;
    float var = g_bnsq[c] / (float)n - mu * mu;
    float sc = gamma[c] * rsqrtf(var + BN_EPS);
    g_bnscale[c] = sc;
    g_bnshift[c] = beta[c] - mu * sc;
}

// apply BN + ELU, then round to tf32 value (h only feeds the next GEMM's A)
__global__ void k_bn_apply_elu(float* __restrict__ x, int n) {
    int i = blockIdx.x * blockDim.x + threadIdx.x;
    if (i >= n * HCOL) return;
    int c = i & (HCOL - 1);
    float v = x[i] * g_bnscale[c] + g_bnshift[c];
    v = (v > 0.f) ? v : expm1f(v);
    x[i] = __uint_as_float(f2tf32(v));
}

// ---------------- launch ----------------
extern "C" void kernel_launch(void* const* d_in, const int* in_sizes, int n_in,
                              void* d_out, int out_size)
{
    const float* x      = (const float*)d_in[0];
    const int*   ei     = (const int*)  d_in[1];
    const float* W1     = (const float*)d_in[2];
    const float* a_src1 = (const float*)d_in[3];
    const float* a_dst1 = (const float*)d_in[4];
    const float* b1     = (const float*)d_in[5];
    const float* g1     = (const float*)d_in[6];
    const float* be1    = (const float*)d_in[7];
    const float* W2     = (const float*)d_in[8];
    const float* a_src2 = (const float*)d_in[9];
    const float* a_dst2 = (const float*)d_in[10];
    const float* b2     = (const float*)d_in[11];
    const float* g2     = (const float*)d_in[12];
    const float* be2    = (const float*)d_in[13];
    const float* W3     = (const float*)d_in[14];
    const float* a_src3 = (const float*)d_in[15];
    const float* a_dst3 = (const float*)d_in[16];
    const float* b3     = (const float*)d_in[17];
    float* out = (float*)d_out;

    float *xp, *h, *s, *d, *al, *xr, *wr;
    cudaGetSymbolAddress((void**)&xp, g_xp);
    cudaGetSymbolAddress((void**)&h,  g_h);
    cudaGetSymbolAddress((void**)&s,  g_s);
    cudaGetSymbolAddress((void**)&d,  g_d);
    cudaGetSymbolAddress((void**)&al, g_alpha);
    cudaGetSymbolAddress((void**)&xr, g_xr);
    cudaGetSymbolAddress((void**)&wr, g_wr);

    static int inited = 0;
    static cudaStream_t s2;
    static cudaEvent_t evFork, evJoin;
    if (!inited) {
        cudaFuncSetAttribute(k_gemm_tf32, cudaFuncAttributeMaxDynamicSharedMemorySize, SMEM_GEMM);
        cudaStreamCreateWithFlags(&s2, cudaStreamNonBlocking);
        cudaEventCreateWithFlags(&evFork, cudaEventDisableTiming);
        cudaEventCreateWithFlags(&evJoin, cudaEventDisableTiming);
        inited = 1;
    }

    const int n = NNODES;

    // ---- fork: CSR build on side stream, overlapped with rounding + gemm1 ----
    cudaEventRecord(evFork, 0);
    cudaStreamWaitEvent(s2, evFork, 0);
    k_init_deg<<<(n + 255) / 256, 256, 0, s2>>>();
    k_hist<<<(NEDGES + 255) / 256, 256, 0, s2>>>(ei);
    k_scan<<<1, 1024, 0, s2>>>();
    k_scatter<<<(NEDGES + n + 255) / 256, 256, 0, s2>>>(ei);
    cudaEventRecord(evJoin, s2);

    // ---- main stream: pre-round inputs to tf32 values ----
    k_round_tf32<<<(NNODES * IN1 / 4 + 255) / 256, 256>>>(x, xr, NNODES * IN1 / 4);
    k_round_tf32<<<(IN1 * HCOL / 4 + 255) / 256, 256>>>(W1, wr, IN1 * HCOL / 4);
    k_round_tf32<<<(HCOL * HCOL / 4 + 255) / 256, 256>>>(W2, wr + W2R_OFF, HCOL * HCOL / 4);
    k_round_tf32<<<(HCOL * C3 / 4 + 255) / 256, 256>>>(W3, wr + W3R_OFF, HCOL * C3 / 4);

    dim3 gemmGrid(4, (n + 127) / 128);
    int warpBlocks12 = (n * H12 * 32 + 255) / 256;   // warp per (node,head)
    int warpBlocks3  = (n * 32 + 255) / 256;

    // ---- layer 1 ----
    k_gemm_tf32<<<gemmGrid, 256, SMEM_GEMM>>>(xr, wr, xp, n, IN1, HCOL, HCOL);
    k_logits<<<warpBlocks12, 256>>>(xp, a_src1, a_dst1, s, d, n, H12, C12, HCOL);
    cudaStreamWaitEvent(0, evJoin, 0);      // CSR ready before alpha/agg
    k_alpha<<<warpBlocks12, 256>>>(s, d, al, n, H12);
    k_agg2<1, false><<<warpBlocks12, 256>>>(xp, al, b1, h, n, H12, C12, HCOL, HCOL);
    k_bn_zero<<<2, 256>>>();
    k_bn_stats<<<(n + 63) / 64, 256>>>(h, n);
    k_bn_finalize<<<2, 256>>>(g1, be1, n);
    k_bn_apply_elu<<<(n * HCOL + 255) / 256, 256>>>(h, n);

    // ---- layer 2 ----
    k_gemm_tf32<<<gemmGrid, 256, SMEM_GEMM>>>(h, wr + W2R_OFF, xp, n, HCOL, HCOL, HCOL);
    k_logits<<<warpBlocks12, 256>>>(xp, a_src2, a_dst2, s, d, n, H12, C12, HCOL);
    k_alpha<<<warpBlocks12, 256>>>(s, d, al, n, H12);
    k_agg2<1, false><<<warpBlocks12, 256>>>(xp, al, b2, h, n, H12, C12, HCOL, HCOL);
    k_bn_zero<<<2, 256>>>();
    k_bn_stats<<<(n + 63) / 64, 256>>>(h, n);
    k_bn_finalize<<<2, 256>>>(g2, be2, n);
    k_bn_apply_elu<<<(n * HCOL + 255) / 256, 256>>>(h, n);

    // ---- layer 3 (H=1, C=500, mean over 1 head == identity) ----
    k_gemm_tf32<<<gemmGrid, 256, SMEM_GEMM>>>(h, wr + W3R_OFF, xp, n, HCOL, C3, C3);
    k_logits<<<warpBlocks3, 256>>>(xp, a_src3, a_dst3, s, d, n, 1, C3, C3);
    k_alpha<<<warpBlocks3, 256>>>(s, d, al, n, 1);
    k_agg2<4, true><<<warpBlocks3, 256>>>(xp, al, b3, out, n, 1, C3, C3, C3);
}

// round 16
// speedup vs baseline: 2.4271x; 1.0168x over previous
#include <cuda_runtime.h>
#include <math.h>
#include <stdint.h>

#define NNODES 10000
#define NEDGES 320000
#define ETOT   (NNODES + NEDGES)
#define HCOL   512          // HID*HEADS
#define H12    4
#define C12    128
#define C3     500
#define IN1    1280
#define BN_EPS 1e-5f
#define NEG_SLOPE 0.2f

#define NEG_INF __int_as_float(0xff800000)

// ---------------- scratch (static __device__, no allocation) ----------------
__device__ float g_xp[NNODES * HCOL];      // transformed features (ld=500 for L3)
__device__ float g_h [NNODES * HCOL];      // aggregated / activated features
__device__ float g_s [NNODES * H12];
__device__ float g_d [NNODES * H12];
__device__ float g_alpha[ETOT * H12];      // normalized attention per (csr pos, head)
__device__ float g_xr[NNODES * IN1];       // tf32-rounded x
__device__ float g_wr[IN1 * HCOL + HCOL * HCOL + HCOL * C3];  // tf32-rounded W1|W2|W3
__device__ int   g_deg[NNODES];
__device__ int   g_off[NNODES + 1];
__device__ int   g_cur[NNODES];
__device__ int   g_csr[ETOT];
__device__ float g_bnsum[HCOL], g_bnsq[HCOL], g_bnscale[HCOL], g_bnshift[HCOL];

#define W2R_OFF (IN1 * HCOL)
#define W3R_OFF (IN1 * HCOL + HCOL * HCOL)

__device__ __forceinline__ uint32_t f2tf32(float x) {
    uint32_t r;
    asm("cvt.rna.tf32.f32 %0, %1;" : "=r"(r) : "f"(x));
    return r;
}

// ---------------- tf32 pre-rounding (float4) ----------------
__global__ void k_round_tf32(const float* __restrict__ in, float* __restrict__ out, int n4) {
    int i = blockIdx.x * blockDim.x + threadIdx.x;
    if (i >= n4) return;
    float4 v = ((const float4*)in)[i];
    float4 o;
    o.x = __uint_as_float(f2tf32(v.x));
    o.y = __uint_as_float(f2tf32(v.y));
    o.z = __uint_as_float(f2tf32(v.z));
    o.w = __uint_as_float(f2tf32(v.w));
    ((float4*)out)[i] = o;
}

// ---------------- CSR build ----------------
__global__ void k_init_deg() {
    int i = blockIdx.x * blockDim.x + threadIdx.x;
    if (i < NNODES) g_deg[i] = 1;          // self loop
}

__global__ void k_hist(const int* __restrict__ ei) {
    int i = blockIdx.x * blockDim.x + threadIdx.x;
    if (i < NEDGES) atomicAdd(&g_deg[ei[NEDGES + i]], 1);   // dst row
}

__global__ void k_scan() {                  // single block, 1024 threads
    __shared__ int sm[1024];
    __shared__ int carry;
    int t = threadIdx.x;
    if (t == 0) carry = 0;
    __syncthreads();
    for (int base = 0; base < NNODES; base += 1024) {
        int i = base + t;
        int v = (i < NNODES) ? g_deg[i] : 0;
        sm[t] = v; __syncthreads();
        for (int off = 1; off < 1024; off <<= 1) {
            int tv = (t >= off) ? sm[t - off] : 0;
            __syncthreads();
            sm[t] += tv;
            __syncthreads();
        }
        int excl = sm[t] - v;
        if (i < NNODES) { g_off[i] = carry + excl; g_cur[i] = carry + excl; }
        __syncthreads();
        if (t == 1023) carry += sm[1023];
        __syncthreads();
    }
    if (t == 0) g_off[NNODES] = carry;      // = ETOT
}

__global__ void k_scatter(const int* __restrict__ ei) {
    int i = blockIdx.x * blockDim.x + threadIdx.x;
    if (i < NEDGES) {
        int s = ei[i], dst = ei[NEDGES + i];
        int p = atomicAdd(&g_cur[dst], 1);
        g_csr[p] = s;
    } else if (i < NEDGES + NNODES) {
        int nid = i - NEDGES;               // self loop
        int p = atomicAdd(&g_cur[nid], 1);
        g_csr[p] = nid;
    }
}

// ---------------- TF32 tensor-core GEMM, cp.async 2-stage, 2 CTAs/SM ----------------
// Inputs pre-rounded to tf32 values -> no cvt in the inner loop.
#define AS_STRIDE 36
#define BS_STRIDE 136
#define A_TILE (128 * AS_STRIDE)
#define B_TILE (32 * BS_STRIDE)
#define NSTAGE 2
#define SMEM_GEMM (NSTAGE * (A_TILE + B_TILE) * 4)

__device__ __forceinline__ void mma_tf32(float* c, const uint32_t* a, const uint32_t* b) {
    asm volatile(
        "mma.sync.aligned.m16n8k8.row.col.f32.tf32.tf32.f32 "
        "{%0,%1,%2,%3}, {%4,%5,%6,%7}, {%8,%9}, {%0,%1,%2,%3};"
        : "+f"(c[0]), "+f"(c[1]), "+f"(c[2]), "+f"(c[3])
        : "r"(a[0]), "r"(a[1]), "r"(a[2]), "r"(a[3]), "r"(b[0]), "r"(b[1]));
}

__device__ __forceinline__ void cp16(float* dst, const float* src) {
    uint32_t d = (uint32_t)__cvta_generic_to_shared(dst);
    asm volatile("cp.async.cg.shared.global [%0], [%1], 16;"
                 :: "r"(d), "l"(src) : "memory");
}

__device__ __forceinline__ void load_tile(
    const float* __restrict__ A, const float* __restrict__ B,
    int M, int K, int Ncols, int row0, int col0, int k0,
    float* As_st, float* Bs_st, int tid)
{
#pragma unroll
    for (int it = 0; it < 4; it++) {
        int e = tid + it * 256;             // 0..1023
        int r = e >> 3;                     // 0..127
        int kc = (e & 7) * 4;
        int gr = row0 + r;
        if (gr >= M) gr = M - 1;            // clamp: garbage rows never stored
        cp16(As_st + r * AS_STRIDE + kc, A + (size_t)gr * K + k0 + kc);
    }
#pragma unroll
    for (int it = 0; it < 4; it++) {
        int e = tid + it * 256;
        int kr = e >> 5;                    // 0..31
        int nc = (e & 31) * 4;
        int gc = col0 + nc;
        if (gc >= Ncols) gc = Ncols - 4;    // clamp: garbage cols never stored
        cp16(Bs_st + kr * BS_STRIDE + nc, B + (size_t)(k0 + kr) * Ncols + gc);
    }
}

__global__ __launch_bounds__(256, 2) void k_gemm_tf32(
    const float* __restrict__ A, const float* __restrict__ B, float* __restrict__ C,
    int M, int K, int Ncols, int ldc)
{
    extern __shared__ float smp[];
    float* As = smp;                        // [NSTAGE][A_TILE]
    float* Bs = smp + NSTAGE * A_TILE;      // [NSTAGE][B_TILE]

    int tid  = threadIdx.x;
    int warp = tid >> 5, lane = tid & 31;
    int lr = lane >> 2, lc = lane & 3;
    int row0 = blockIdx.y * 128, col0 = blockIdx.x * 128;
    int wm = (warp & 3) * 32;               // warp m-offset
    int wn = (warp >> 2) * 64;              // warp n-offset

    float acc[2][8][4];
#pragma unroll
    for (int i = 0; i < 2; i++)
#pragma unroll
        for (int j = 0; j < 8; j++)
#pragma unroll
            for (int r = 0; r < 4; r++) acc[i][j][r] = 0.f;

    int T = K >> 5;                         // K % 32 == 0 always

    load_tile(A, B, M, K, Ncols, row0, col0, 0, As, Bs, tid);
    asm volatile("cp.async.commit_group;" ::: "memory");

    for (int kt = 0; kt < T; kt++) {
        if (kt + 1 < T) {
            int st = (kt + 1) & 1;
            load_tile(A, B, M, K, Ncols, row0, col0, (kt + 1) * 32,
                      As + st * A_TILE, Bs + st * B_TILE, tid);
        }
        asm volatile("cp.async.commit_group;" ::: "memory");
        asm volatile("cp.async.wait_group 1;" ::: "memory");
        __syncthreads();

        const float* a_s = As + (kt & 1) * A_TILE;
        const float* b_s = Bs + (kt & 1) * B_TILE;

#pragma unroll
        for (int kk = 0; kk < 32; kk += 8) {
            uint32_t af[2][4], bf[8][2];
#pragma unroll
            for (int mi = 0; mi < 2; mi++) {
                int m = wm + mi * 16;
                af[mi][0] = __float_as_uint(a_s[(m + lr    ) * AS_STRIDE + kk + lc    ]);
                af[mi][1] = __float_as_uint(a_s[(m + lr + 8) * AS_STRIDE + kk + lc    ]);
                af[mi][2] = __float_as_uint(a_s[(m + lr    ) * AS_STRIDE + kk + lc + 4]);
                af[mi][3] = __float_as_uint(a_s[(m + lr + 8) * AS_STRIDE + kk + lc + 4]);
            }
#pragma unroll
            for (int ni = 0; ni < 8; ni++) {
                int nn = wn + ni * 8;
                bf[ni][0] = __float_as_uint(b_s[(kk + lc    ) * BS_STRIDE + nn + lr]);
                bf[ni][1] = __float_as_uint(b_s[(kk + lc + 4) * BS_STRIDE + nn + lr]);
            }
#pragma unroll
            for (int mi = 0; mi < 2; mi++)
#pragma unroll
                for (int ni = 0; ni < 8; ni++)
                    mma_tf32(acc[mi][ni], af[mi], bf[ni]);
        }
        __syncthreads();
    }

    // --- store C (Ncols % 4 == 0 -> float2 pairs stay in-bounds together) ---
#pragma unroll
    for (int mi = 0; mi < 2; mi++) {
#pragma unroll
        for (int ni = 0; ni < 8; ni++) {
            int colb = col0 + wn + ni * 8 + lc * 2;
            if (colb >= Ncols) continue;
#pragma unroll
            for (int hh = 0; hh < 2; hh++) {
                int r = row0 + wm + mi * 16 + lr + hh * 8;
                if (r < M) {
                    float2 v = make_float2(acc[mi][ni][hh * 2], acc[mi][ni][hh * 2 + 1]);
                    *(float2*)(C + (size_t)r * ldc + colb) = v;
                }
            }
        }
    }
}

// ---------------- per-(node,head) attention logits (float4) ----------------
__global__ void k_logits(const float* __restrict__ xp, const float* __restrict__ a_src,
                         const float* __restrict__ a_dst, float* __restrict__ s,
                         float* __restrict__ d, int n, int H, int C, int ld)
{
    int w = (blockIdx.x * blockDim.x + threadIdx.x) >> 5;
    int lane = threadIdx.x & 31;
    if (w >= n * H) return;
    int node = w / H, h = w - node * H;
    int C4 = C >> 2;                        // C % 4 == 0 (128, 500)
    const float4* row = (const float4*)(xp + (size_t)node * ld + h * C);
    const float4* as4 = (const float4*)(a_src + h * C);
    const float4* ad4 = (const float4*)(a_dst + h * C);
    float ss = 0.f, dd = 0.f;
    for (int c = lane; c < C4; c += 32) {
        float4 v = row[c], a = as4[c], b = ad4[c];
        ss += v.x * a.x + v.y * a.y + v.z * a.z + v.w * a.w;
        dd += v.x * b.x + v.y * b.y + v.z * b.z + v.w * b.w;
    }
#pragma unroll
    for (int o = 16; o; o >>= 1) {
        ss += __shfl_xor_sync(0xffffffffu, ss, o);
        dd += __shfl_xor_sync(0xffffffffu, dd, o);
    }
    if (lane == 0) { s[w] = ss; d[w] = dd; }
}

// ---- pass 1: normalized attention weights, warp per (node,head), lanes over edges ----
__global__ void k_alpha(const float* __restrict__ s, const float* __restrict__ dl,
                        float* __restrict__ alpha, int n, int H)
{
    int w = (blockIdx.x * blockDim.x + threadIdx.x) >> 5;
    int lane = threadIdx.x & 31;
    if (w >= n * H) return;
    int node = w / H, h = w - node * H;
    float dn = dl[w];
    int beg = g_off[node], end = g_off[node + 1];

    float m = NEG_INF;
    for (int idx = beg + lane; idx < end; idx += 32) {
        int src = g_csr[idx];
        float e = s[src * H + h] + dn;
        e = (e > 0.f) ? e : NEG_SLOPE * e;
        m = fmaxf(m, e);
    }
#pragma unroll
    for (int o = 16; o; o >>= 1) m = fmaxf(m, __shfl_xor_sync(0xffffffffu, m, o));

    float zz = 0.f;
    for (int idx = beg + lane; idx < end; idx += 32) {
        int src = g_csr[idx];
        float e = s[src * H + h] + dn;
        e = (e > 0.f) ? e : NEG_SLOPE * e;
        float p = __expf(e - m);
        alpha[(size_t)idx * H + h] = p;
        zz += p;
    }
#pragma unroll
    for (int o = 16; o; o >>= 1) zz += __shfl_xor_sync(0xffffffffu, zz, o);

    float inv = 1.f / zz;
    for (int idx = beg + lane; idx < end; idx += 32)
        alpha[(size_t)idx * H + h] *= inv;
}

// ---- pass 2: pure weighted gather, warp per (node,head), float4 per lane ----
template <int NCH, bool GUARD>
__global__ void k_agg2(const float* __restrict__ xp, const float* __restrict__ alpha,
                       const float* __restrict__ bias, float* __restrict__ out,
                       int n, int H, int C, int ldxp, int ldout)
{
    int w = (blockIdx.x * blockDim.x + threadIdx.x) >> 5;
    int lane = threadIdx.x & 31;
    if (w >= n * H) return;
    int node = w / H, h = w - node * H;
    int C4 = C >> 2;
    float4 acc[NCH];
#pragma unroll
    for (int r = 0; r < NCH; r++) acc[r] = make_float4(0.f, 0.f, 0.f, 0.f);
    int beg = g_off[node], end = g_off[node + 1];

#pragma unroll 2
    for (int idx = beg; idx < end; idx++) {
        int src = g_csr[idx];
        float a = alpha[(size_t)idx * H + h];
        const float4* row = (const float4*)(xp + (size_t)src * ldxp + h * C);
#pragma unroll
        for (int r = 0; r < NCH; r++) {
            int ch = lane + r * 32;
            float4 v = (!GUARD || ch < C4) ? row[ch] : make_float4(0.f, 0.f, 0.f, 0.f);
            acc[r].x += a * v.x;
            acc[r].y += a * v.y;
            acc[r].z += a * v.z;
            acc[r].w += a * v.w;
        }
    }

    const float4* brow = (const float4*)(bias + h * C);
    float4* orow = (float4*)(out + (size_t)node * ldout + h * C);
#pragma unroll
    for (int r = 0; r < NCH; r++) {
        int ch = lane + r * 32;
        if (!GUARD || ch < C4) {
            float4 bv = brow[ch];
            float4 o;
            o.x = acc[r].x + bv.x;
            o.y = acc[r].y + bv.y;
            o.z = acc[r].z + bv.z;
            o.w = acc[r].w + bv.w;
            orow[ch] = o;
        }
    }
}

// ---------------- batch norm + ELU ----------------
__global__ void k_bn_zero() {
    int i = blockIdx.x * blockDim.x + threadIdx.x;
    if (i < HCOL) { g_bnsum[i] = 0.f; g_bnsq[i] = 0.f; }
}

__global__ __launch_bounds__(256) void k_bn_stats(const float* __restrict__ x, int n) {
    int tid = threadIdx.x;                  // owns cols tid, tid+256
    int r0 = blockIdx.x * 64;
    int r1 = min(r0 + 64, n);
    float s0 = 0.f, s1 = 0.f, q0 = 0.f, q1 = 0.f;
    for (int r = r0; r < r1; r++) {
        float v0 = x[(size_t)r * HCOL + tid];
        float v1 = x[(size_t)r * HCOL + tid + 256];
        s0 += v0; q0 += v0 * v0;
        s1 += v1; q1 += v1 * v1;
    }
    atomicAdd(&g_bnsum[tid],       s0);
    atomicAdd(&g_bnsq [tid],       q0);
    atomicAdd(&g_bnsum[tid + 256], s1);
    atomicAdd(&g_bnsq [tid + 256], q1);
}

__global__ void k_bn_finalize(const float* __restrict__ gamma, const float* __restrict__ beta, int n) {
    int c = blockIdx.x * blockDim.x + threadIdx.x;
    if (c >= HCOL) return;
    float mu = g_bnsum[c] / (float)n;
    float var = g_bnsq[c] / (float)n - mu * mu;
    float sc = gamma[c] * rsqrtf(var + BN_EPS);
    g_bnscale[c] = sc;
    g_bnshift[c] = beta[c] - mu * sc;
}

// apply BN + ELU, then round to tf32 value (h only feeds the next GEMM's A)
__global__ void k_bn_apply_elu(float* __restrict__ x, int n) {
    int i = blockIdx.x * blockDim.x + threadIdx.x;
    if (i >= n * HCOL) return;
    int c = i & (HCOL - 1);
    float v = x[i] * g_bnscale[c] + g_bnshift[c];
    v = (v > 0.f) ? v : expm1f(v);
    x[i] = __uint_as_float(f2tf32(v));
}

// ---------------- launch ----------------
extern "C" void kernel_launch(void* const* d_in, const int* in_sizes, int n_in,
                              void* d_out, int out_size)
{
    const float* x      = (const float*)d_in[0];
    const int*   ei     = (const int*)  d_in[1];
    const float* W1     = (const float*)d_in[2];
    const float* a_src1 = (const float*)d_in[3];
    const float* a_dst1 = (const float*)d_in[4];
    const float* b1     = (const float*)d_in[5];
    const float* g1     = (const float*)d_in[6];
    const float* be1    = (const float*)d_in[7];
    const float* W2     = (const float*)d_in[8];
    const float* a_src2 = (const float*)d_in[9];
    const float* a_dst2 = (const float*)d_in[10];
    const float* b2     = (const float*)d_in[11];
    const float* g2     = (const float*)d_in[12];
    const float* be2    = (const float*)d_in[13];
    const float* W3     = (const float*)d_in[14];
    const float* a_src3 = (const float*)d_in[15];
    const float* a_dst3 = (const float*)d_in[16];
    const float* b3     = (const float*)d_in[17];
    float* out = (float*)d_out;

    float *xp, *h, *s, *d, *al, *xr, *wr;
    cudaGetSymbolAddress((void**)&xp, g_xp);
    cudaGetSymbolAddress((void**)&h,  g_h);
    cudaGetSymbolAddress((void**)&s,  g_s);
    cudaGetSymbolAddress((void**)&d,  g_d);
    cudaGetSymbolAddress((void**)&al, g_alpha);
    cudaGetSymbolAddress((void**)&xr, g_xr);
    cudaGetSymbolAddress((void**)&wr, g_wr);

    static int inited = 0;
    static cudaStream_t s2;
    static cudaEvent_t evFork, evJoin;
    if (!inited) {
        cudaFuncSetAttribute(k_gemm_tf32, cudaFuncAttributeMaxDynamicSharedMemorySize, SMEM_GEMM);
        cudaStreamCreateWithFlags(&s2, cudaStreamNonBlocking);
        cudaEventCreateWithFlags(&evFork, cudaEventDisableTiming);
        cudaEventCreateWithFlags(&evJoin, cudaEventDisableTiming);
        inited = 1;
    }

    const int n = NNODES;

    // ---- fork: W2/W3 rounding + CSR build on side stream ----
    cudaEventRecord(evFork, 0);
    cudaStreamWaitEvent(s2, evFork, 0);
    k_round_tf32<<<(HCOL * HCOL / 4 + 255) / 256, 256, 0, s2>>>(W2, wr + W2R_OFF, HCOL * HCOL / 4);
    k_round_tf32<<<(HCOL * C3 / 4 + 255) / 256, 256, 0, s2>>>(W3, wr + W3R_OFF, HCOL * C3 / 4);
    k_init_deg<<<(n + 255) / 256, 256, 0, s2>>>();
    k_hist<<<(NEDGES + 255) / 256, 256, 0, s2>>>(ei);
    k_scan<<<1, 1024, 0, s2>>>();
    k_scatter<<<(NEDGES + n + 255) / 256, 256, 0, s2>>>(ei);
    cudaEventRecord(evJoin, s2);

    // ---- main stream: pre-round GEMM1 inputs ----
    k_round_tf32<<<(NNODES * IN1 / 4 + 255) / 256, 256>>>(x, xr, NNODES * IN1 / 4);
    k_round_tf32<<<(IN1 * HCOL / 4 + 255) / 256, 256>>>(W1, wr, IN1 * HCOL / 4);

    dim3 gemmGrid(4, (n + 127) / 128);
    int warpBlocks12 = (n * H12 * 32 + 255) / 256;   // warp per (node,head)
    int warpBlocks3  = (n * 32 + 255) / 256;

    // ---- layer 1 ----
    k_gemm_tf32<<<gemmGrid, 256, SMEM_GEMM>>>(xr, wr, xp, n, IN1, HCOL, HCOL);
    k_logits<<<warpBlocks12, 256>>>(xp, a_src1, a_dst1, s, d, n, H12, C12, HCOL);
    cudaStreamWaitEvent(0, evJoin, 0);      // CSR + W2/W3 ready
    k_alpha<<<warpBlocks12, 256>>>(s, d, al, n, H12);
    k_agg2<1, false><<<warpBlocks12, 256>>>(xp, al, b1, h, n, H12, C12, HCOL, HCOL);
    k_bn_zero<<<2, 256>>>();
    k_bn_stats<<<(n + 63) / 64, 256>>>(h, n);
    k_bn_finalize<<<2, 256>>>(g1, be1, n);
    k_bn_apply_elu<<<(n * HCOL + 255) / 256, 256>>>(h, n);

    // ---- layer 2 ----
    k_gemm_tf32<<<gemmGrid, 256, SMEM_GEMM>>>(h, wr + W2R_OFF, xp, n, HCOL, HCOL, HCOL);
    k_logits<<<warpBlocks12, 256>>>(xp, a_src2, a_dst2, s, d, n, H12, C12, HCOL);
    k_alpha<<<warpBlocks12, 256>>>(s, d, al, n, H12);
    k_agg2<1, false><<<warpBlocks12, 256>>>(xp, al, b2, h, n, H12, C12, HCOL, HCOL);
    k_bn_zero<<<2, 256>>>();
    k_bn_stats<<<(n + 63) / 64, 256>>>(h, n);
    k_bn_finalize<<<2, 256>>>(g2, be2, n);
    k_bn_apply_elu<<<(n * HCOL + 255) / 256, 256>>>(h, n);

    // ---- layer 3 (H=1, C=500, mean over 1 head == identity) ----
    k_gemm_tf32<<<gemmGrid, 256, SMEM_GEMM>>>(h, wr + W3R_OFF, xp, n, HCOL, C3, C3);
    k_logits<<<warpBlocks3, 256>>>(xp, a_src3, a_dst3, s, d, n, 1, C3, C3);
    k_alpha<<<warpBlocks3, 256>>>(s, d, al, n, 1);
    k_agg2<4, true><<<warpBlocks3, 256>>>(xp, al, b3, out, n, 1, C3, C3, C3);
}